// round 4
// baseline (speedup 1.0000x reference)
#include <cuda_runtime.h>
#include <cuda_bf16.h>
#include <math.h>

#define NN 20000
#define EE 320000
#define ET (EE + NN)
#define FIN 128
#define F2C 64
#define HC 8
#define D1 512
#define G4 256

// ---------------- scratch ----------------------------------------------------
__device__ float g_v1[FIN * 16];       // folded attn vectors layer1 [k][16]
__device__ float g_v2[F2C * 16];       // folded attn vectors layer2 [k][16]
__device__ float g_gb[G4];             // bias1@W_ih^T + b_ih + b_hh
__device__ float g_Wiht[D1 * G4];      // W_ih transposed [512,256]
__device__ float g_aggX[NN * HC * FIN];// per-head gathered x  [N,8,128]
__device__ float g_agg1[NN * D1];      // GAT1 output [N,512]
__device__ float g_gates[NN * G4];
__device__ float g_h2[NN * F2C];
__device__ float g_aggC[NN * HC * F2C];// per-head gathered h2 [N,8,64]
__device__ float g_pre[NN * D1];       // pre-softmax
__device__ float g_as[NN * HC];
__device__ float g_ad[NN * HC];
__device__ float g_m[NN * HC];
__device__ float g_den[NN * HC];
__device__ int   g_deg[NN];
__device__ int   g_offs[NN + 1];
__device__ int   g_cur[NN];
__device__ int   g_csrc[ET];

__device__ __forceinline__ float sigf(float x) { return 1.0f / (1.0f + __expf(-x)); }
__device__ __forceinline__ unsigned f2tf(float f) {
    unsigned u;
    asm("cvt.rna.tf32.f32 %0, %1;" : "=r"(u) : "f"(f));
    return u;
}

// ---------------- CSR build (proven) ------------------------------------------
__global__ void k_degree(const int* __restrict__ ei, int E) {
    int i = blockIdx.x * blockDim.x + threadIdx.x;
    if (i >= E + NN) return;
    int dst = (i < E) ? ei[E + i] : (i - E);
    atomicAdd(&g_deg[dst], 1);
}

__global__ void k_scan() {
    __shared__ int sums[1024];
    const int CH = 20;
    int t = threadIdx.x;
    int b = t * CH;
    int e = min(b + CH, NN);
    int tmp[CH];
    int local = 0;
    for (int i = b; i < e; i++) { tmp[i - b] = g_deg[i]; local += tmp[i - b]; }
    sums[t] = local;
    __syncthreads();
    for (int o = 1; o < 1024; o <<= 1) {
        int v = (t >= o) ? sums[t - o] : 0;
        __syncthreads();
        sums[t] += v;
        __syncthreads();
    }
    int run = sums[t] - local;
    for (int i = b; i < e; i++) {
        g_offs[i] = run;
        g_cur[i]  = run;
        run += tmp[i - b];
    }
    if (b < NN && e == NN) g_offs[NN] = run;
}

__global__ void k_scatter(const int* __restrict__ ei, int E) {
    int i = blockIdx.x * blockDim.x + threadIdx.x;
    if (i >= E + NN) return;
    int src, dst;
    if (i < E) { src = ei[i]; dst = ei[E + i]; }
    else       { src = dst = i - E; }
    int pos = atomicAdd(&g_cur[dst], 1);
    g_csrc[pos] = src;
}

// ---------------- folds (exact fp32) ------------------------------------------
__global__ void k_transpose(const float* __restrict__ Wih) {
    int idx = blockIdx.x * blockDim.x + threadIdx.x;
    if (idx >= G4 * D1) return;
    int j = idx >> 9;
    int k = idx & 511;
    g_Wiht[k * G4 + j] = Wih[idx];
}

// V[k][col]: col<8 -> sum_f W[k, h*64+f]*att_src[h*64+f]; col>=8 -> att_dst
__global__ void k_fold_attn(const float* __restrict__ W, const float* __restrict__ asrc,
                            const float* __restrict__ adst, float* __restrict__ V, int K) {
    int idx = blockIdx.x * blockDim.x + threadIdx.x;
    if (idx >= K * 16) return;
    int k = idx >> 4;
    int col = idx & 15;
    int h = col & 7;
    const float* att = (col & 8) ? adst : asrc;
    float acc = 0.f;
#pragma unroll 8
    for (int f = 0; f < F2C; f++)
        acc += W[(long)k * D1 + h * F2C + f] * att[h * F2C + f];
    V[idx] = acc;
}

__global__ void k_foldb(const float* __restrict__ bias1, const float* __restrict__ b_ih,
                        const float* __restrict__ b_hh) {
    int j = threadIdx.x;
    float acc = b_ih[j] + b_hh[j];
    for (int d = 0; d < D1; d++) acc += bias1[d] * g_Wiht[d * G4 + j];
    g_gb[j] = acc;
}

// ---------------- attention logits: a[n,h] = feat[n]·V[:,h] (exact fp32) ------
template <int K>
__global__ __launch_bounds__(256) void k_attnx(const float* __restrict__ feat,
                                               const float* __restrict__ V) {
    __shared__ float sV[K * 17];
    int tid = threadIdx.x;
    for (int idx = tid; idx < K * 16; idx += 256) {
        int k = idx >> 4, c = idx & 15;
        sV[k * 17 + c] = V[idx];
    }
    __syncthreads();
    int warp = tid >> 5, lane = tid & 31;
    int n = blockIdx.x * 8 + warp;
    if (n >= NN) return;
    float xv[K / 32];
#pragma unroll
    for (int c = 0; c < K / 32; c++) xv[c] = feat[(long)n * K + c * 32 + lane];
    float acc[16];
#pragma unroll
    for (int h = 0; h < 16; h++) acc[h] = 0.f;
#pragma unroll
    for (int c = 0; c < K / 32; c++) {
        int k = c * 32 + lane;
#pragma unroll
        for (int h = 0; h < 16; h++) acc[h] += xv[c] * sV[k * 17 + h];
    }
#pragma unroll
    for (int off = 16; off > 0; off >>= 1)
#pragma unroll
        for (int h = 0; h < 16; h++)
            acc[h] += __shfl_xor_sync(0xffffffffu, acc[h], off);
    if (lane == 0) {
#pragma unroll
        for (int h = 0; h < 8; h++) {
            g_as[n * HC + h] = acc[h];
            g_ad[n * HC + h] = acc[8 + h];
        }
    }
}

// ---------------- per (node,head) online softmax stats (proven R2) ------------
__global__ void k_stats() {
    int idx = blockIdx.x * blockDim.x + threadIdx.x;
    if (idx >= NN * HC) return;
    int n = idx >> 3, h = idx & 7;
    float adn = g_ad[idx];
    int beg = g_offs[n], end = g_offs[n + 1];
    int src = g_csrc[beg];
    float e = g_as[src * HC + h] + adn;
    e = (e > 0.f) ? e : 0.2f * e;
    float mx = e, s = 1.0f;
    for (int j = beg + 1; j < end; j++) {
        src = g_csrc[j];
        e = g_as[src * HC + h] + adn;
        e = (e > 0.f) ? e : 0.2f * e;
        if (e > mx) { s *= __expf(mx - e); mx = e; }
        s += __expf(e - mx);
    }
    g_m[idx] = mx;
    g_den[idx] = s;
}

// ---------------- per-head gathers --------------------------------------------
// layer1: warp per node; lane: head = lane>>2, quad q = lane&3 owns x feats [q*32, q*32+32)
// aggX[n, h, k] = sum_e alpha_e[h] * x[src_e, k]
__global__ __launch_bounds__(256) void k_gatherX(const float* __restrict__ x) {
    int warp = threadIdx.x >> 5, lane = threadIdx.x & 31;
    int n = blockIdx.x * 8 + warp;
    if (n >= NN) return;
    int h = lane >> 2;
    int q = lane & 3;
    float adn = g_ad[n * HC + h];
    float mn  = g_m[n * HC + h];
    float inv = 1.0f / (g_den[n * HC + h] + 1e-16f);
    int beg = g_offs[n], end = g_offs[n + 1];
    float4 acc[8];
#pragma unroll
    for (int i = 0; i < 8; i++) acc[i] = make_float4(0.f, 0.f, 0.f, 0.f);
    for (int j = beg; j < end; j++) {
        int s = g_csrc[j];
        float e = g_as[s * HC + h] + adn;
        e = (e > 0.f) ? e : 0.2f * e;
        float alpha = __expf(e - mn) * inv;
        const float4* xp = (const float4*)&x[(long)s * FIN + q * 32];
#pragma unroll
        for (int i = 0; i < 8; i++) {
            float4 v = xp[i];
            acc[i].x += alpha * v.x;
            acc[i].y += alpha * v.y;
            acc[i].z += alpha * v.z;
            acc[i].w += alpha * v.w;
        }
    }
    float4* op = (float4*)&g_aggX[(long)n * (HC * FIN) + h * FIN + q * 32];
#pragma unroll
    for (int i = 0; i < 8; i++) op[i] = acc[i];
}

// layer2: lane: head = lane>>2, quad q owns h2 feats [q*16, q*16+16)
__global__ __launch_bounds__(256) void k_gatherH() {
    int warp = threadIdx.x >> 5, lane = threadIdx.x & 31;
    int n = blockIdx.x * 8 + warp;
    if (n >= NN) return;
    int h = lane >> 2;
    int q = lane & 3;
    float adn = g_ad[n * HC + h];
    float mn  = g_m[n * HC + h];
    float inv = 1.0f / (g_den[n * HC + h] + 1e-16f);
    int beg = g_offs[n], end = g_offs[n + 1];
    float4 acc[4];
#pragma unroll
    for (int i = 0; i < 4; i++) acc[i] = make_float4(0.f, 0.f, 0.f, 0.f);
    for (int j = beg; j < end; j++) {
        int s = g_csrc[j];
        float e = g_as[s * HC + h] + adn;
        e = (e > 0.f) ? e : 0.2f * e;
        float alpha = __expf(e - mn) * inv;
        const float4* xp = (const float4*)&g_h2[(long)s * F2C + q * 16];
#pragma unroll
        for (int i = 0; i < 4; i++) {
            float4 v = xp[i];
            acc[i].x += alpha * v.x;
            acc[i].y += alpha * v.y;
            acc[i].z += alpha * v.z;
            acc[i].w += alpha * v.w;
        }
    }
    float4* op = (float4*)&g_aggC[(long)n * (HC * F2C) + h * F2C + q * 16];
#pragma unroll
    for (int i = 0; i < 4; i++) op[i] = acc[i];
}

// ---------------- TF32 GEMM, 128x128 tile (proven) -----------------------------
__global__ __launch_bounds__(256) void k_tfgemm(int M, int N, int K,
                                                const float* __restrict__ A,
                                                const float* __restrict__ B,
                                                float* __restrict__ C) {
    __shared__ unsigned As[16][136];
    __shared__ unsigned Bs[16][136];
    int tid  = threadIdx.x;
    int lane = tid & 31;
    int warp = tid >> 5;
    int wr = warp & 3;
    int wc = warp >> 2;
    int blockRow = blockIdx.y * 128;
    int blockCol = blockIdx.x * 128;

    float acc[2][8][4];
#pragma unroll
    for (int i = 0; i < 2; i++)
#pragma unroll
        for (int j = 0; j < 8; j++)
#pragma unroll
            for (int q = 0; q < 4; q++) acc[i][j][q] = 0.0f;

    int arow = tid >> 2;
    int acol = (tid & 3) * 4;
    int brow = tid >> 5;
    int bcol = (tid & 31) * 4;

    for (int k0 = 0; k0 < K; k0 += 16) {
#pragma unroll
        for (int half = 0; half < 2; half++) {
            int r = arow + half * 64;
            float4 v = make_float4(0.f, 0.f, 0.f, 0.f);
            if (blockRow + r < M)
                v = *(const float4*)&A[(long)(blockRow + r) * K + k0 + acol];
            As[acol + 0][r] = f2tf(v.x);
            As[acol + 1][r] = f2tf(v.y);
            As[acol + 2][r] = f2tf(v.z);
            As[acol + 3][r] = f2tf(v.w);
        }
#pragma unroll
        for (int half = 0; half < 2; half++) {
            int kr = brow + half * 8;
            float4 v = *(const float4*)&B[(long)(k0 + kr) * N + blockCol + bcol];
            uint4 u = make_uint4(f2tf(v.x), f2tf(v.y), f2tf(v.z), f2tf(v.w));
            *(uint4*)&Bs[kr][bcol] = u;
        }
        __syncthreads();

#pragma unroll
        for (int ks = 0; ks < 16; ks += 8) {
            unsigned a[2][4], b[8][2];
            int r0 = wr * 32 + (lane >> 2);
            int c0 = ks + (lane & 3);
#pragma unroll
            for (int i = 0; i < 2; i++) {
                a[i][0] = As[c0][r0 + i * 16];
                a[i][1] = As[c0][r0 + i * 16 + 8];
                a[i][2] = As[c0 + 4][r0 + i * 16];
                a[i][3] = As[c0 + 4][r0 + i * 16 + 8];
            }
            int bn = wc * 64 + (lane >> 2);
#pragma unroll
            for (int j = 0; j < 8; j++) {
                b[j][0] = Bs[c0][bn + j * 8];
                b[j][1] = Bs[c0 + 4][bn + j * 8];
            }
#pragma unroll
            for (int i = 0; i < 2; i++) {
#pragma unroll
                for (int j = 0; j < 8; j++) {
                    asm volatile(
                        "mma.sync.aligned.m16n8k8.row.col.f32.tf32.tf32.f32 "
                        "{%0,%1,%2,%3}, {%4,%5,%6,%7}, {%8,%9}, {%0,%1,%2,%3};"
                        : "+f"(acc[i][j][0]), "+f"(acc[i][j][1]),
                          "+f"(acc[i][j][2]), "+f"(acc[i][j][3])
                        : "r"(a[i][0]), "r"(a[i][1]), "r"(a[i][2]), "r"(a[i][3]),
                          "r"(b[j][0]), "r"(b[j][1]));
                }
            }
        }
        __syncthreads();
    }

#pragma unroll
    for (int i = 0; i < 2; i++) {
        int r = blockRow + wr * 32 + i * 16 + (lane >> 2);
#pragma unroll
        for (int j = 0; j < 8; j++) {
            int c = blockCol + wc * 64 + j * 8 + (lane & 3) * 2;
            if (r < M)
                *(float2*)&C[(long)r * N + c] = make_float2(acc[i][j][0], acc[i][j][1]);
            if (r + 8 < M)
                *(float2*)&C[(long)(r + 8) * N + c] = make_float2(acc[i][j][2], acc[i][j][3]);
        }
    }
}

// ---------------- batched per-head TF32 GEMM, 128x64 tile ----------------------
// C[r, h*64+c] = sum_k A[r, h*KD + k] * B[k, h*64+c]
// A: [M, 8*KD] (lda = 8*KD), B: [KD, 512] (ldb=512), C: [M, 512]
template <int KD>
__global__ __launch_bounds__(256) void k_tfgemm_h(int M,
                                                  const float* __restrict__ A,
                                                  const float* __restrict__ B,
                                                  float* __restrict__ C) {
    __shared__ unsigned As[16][136];
    __shared__ unsigned Bs[16][72];
    const int lda = 8 * KD;
    int h = blockIdx.z;
    const float* Ap = A + h * KD;
    const float* Bp = B + h * 64;
    float* Cp = C + h * 64;
    int tid  = threadIdx.x;
    int lane = tid & 31;
    int warp = tid >> 5;
    int wr = warp & 3;                 // 32 rows each
    int wc = warp >> 2;                // 32 cols each
    int blockRow = blockIdx.y * 128;

    float acc[2][4][4];
#pragma unroll
    for (int i = 0; i < 2; i++)
#pragma unroll
        for (int j = 0; j < 4; j++)
#pragma unroll
            for (int q = 0; q < 4; q++) acc[i][j][q] = 0.0f;

    int arow = tid >> 2;               // 0..63
    int acol = (tid & 3) * 4;
    int brow = tid >> 4;               // 0..15
    int bcol = (tid & 15) * 4;         // 0..60

    for (int k0 = 0; k0 < KD; k0 += 16) {
#pragma unroll
        for (int half = 0; half < 2; half++) {
            int r = arow + half * 64;
            float4 v = make_float4(0.f, 0.f, 0.f, 0.f);
            if (blockRow + r < M)
                v = *(const float4*)&Ap[(long)(blockRow + r) * lda + k0 + acol];
            As[acol + 0][r] = f2tf(v.x);
            As[acol + 1][r] = f2tf(v.y);
            As[acol + 2][r] = f2tf(v.z);
            As[acol + 3][r] = f2tf(v.w);
        }
        {
            float4 v = *(const float4*)&Bp[(long)(k0 + brow) * D1 + bcol];
            Bs[brow][bcol + 0] = f2tf(v.x);
            Bs[brow][bcol + 1] = f2tf(v.y);
            Bs[brow][bcol + 2] = f2tf(v.z);
            Bs[brow][bcol + 3] = f2tf(v.w);
        }
        __syncthreads();

#pragma unroll
        for (int ks = 0; ks < 16; ks += 8) {
            unsigned a[2][4], b[4][2];
            int r0 = wr * 32 + (lane >> 2);
            int c0 = ks + (lane & 3);
#pragma unroll
            for (int i = 0; i < 2; i++) {
                a[i][0] = As[c0][r0 + i * 16];
                a[i][1] = As[c0][r0 + i * 16 + 8];
                a[i][2] = As[c0 + 4][r0 + i * 16];
                a[i][3] = As[c0 + 4][r0 + i * 16 + 8];
            }
            int bn = wc * 32 + (lane >> 2);
#pragma unroll
            for (int j = 0; j < 4; j++) {
                b[j][0] = Bs[c0][bn + j * 8];
                b[j][1] = Bs[c0 + 4][bn + j * 8];
            }
#pragma unroll
            for (int i = 0; i < 2; i++) {
#pragma unroll
                for (int j = 0; j < 4; j++) {
                    asm volatile(
                        "mma.sync.aligned.m16n8k8.row.col.f32.tf32.tf32.f32 "
                        "{%0,%1,%2,%3}, {%4,%5,%6,%7}, {%8,%9}, {%0,%1,%2,%3};"
                        : "+f"(acc[i][j][0]), "+f"(acc[i][j][1]),
                          "+f"(acc[i][j][2]), "+f"(acc[i][j][3])
                        : "r"(a[i][0]), "r"(a[i][1]), "r"(a[i][2]), "r"(a[i][3]),
                          "r"(b[j][0]), "r"(b[j][1]));
                }
            }
        }
        __syncthreads();
    }

#pragma unroll
    for (int i = 0; i < 2; i++) {
        int r = blockRow + wr * 32 + i * 16 + (lane >> 2);
#pragma unroll
        for (int j = 0; j < 4; j++) {
            int c = wc * 32 + j * 8 + (lane & 3) * 2;
            if (r < M)
                *(float2*)&Cp[(long)r * D1 + c] = make_float2(acc[i][j][0], acc[i][j][1]);
            if (r + 8 < M)
                *(float2*)&Cp[(long)(r + 8) * D1 + c] = make_float2(acc[i][j][2], acc[i][j][3]);
        }
    }
}

// ---------------- LSTM elementwise + relu --------------------------------------
__global__ void k_lstm() {
    int idx = blockIdx.x * blockDim.x + threadIdx.x;
    if (idx >= NN * F2C) return;
    int n = idx >> 6, j = idx & 63;
    const float* g = g_gates + (long)n * G4;
    float i_ = g[j]       + g_gb[j];
    float gg = g[128 + j] + g_gb[128 + j];
    float o_ = g[192 + j] + g_gb[192 + j];
    float c  = sigf(i_) * tanhf(gg);
    float hh = sigf(o_) * tanhf(c);
    g_h2[idx] = fmaxf(hh, 0.0f);
}

// ---------------- bias + row softmax over 512 ----------------------------------
__global__ __launch_bounds__(256) void k_softmax(const float* __restrict__ in,
                                                 const float* __restrict__ bias2,
                                                 float* __restrict__ out) {
    __shared__ float red[256];
    int n = blockIdx.x, t = threadIdx.x;
    float a = in[(long)n * D1 + t] + bias2[t];
    float b = in[(long)n * D1 + 256 + t] + bias2[256 + t];
    red[t] = fmaxf(a, b);
    __syncthreads();
#pragma unroll
    for (int o = 128; o > 0; o >>= 1) {
        if (t < o) red[t] = fmaxf(red[t], red[t + o]);
        __syncthreads();
    }
    float mx = red[0];
    __syncthreads();
    float ea = __expf(a - mx), eb = __expf(b - mx);
    red[t] = ea + eb;
    __syncthreads();
#pragma unroll
    for (int o = 128; o > 0; o >>= 1) {
        if (t < o) red[t] += red[t + o];
        __syncthreads();
    }
    float inv = 1.0f / red[0];
    out[(long)n * D1 + t] = ea * inv;
    out[(long)n * D1 + 256 + t] = eb * inv;
}

// ---------------- launch ---------------------------------------------------------
extern "C" void kernel_launch(void* const* d_in, const int* in_sizes, int n_in,
                              void* d_out, int out_size) {
    const float* x        = (const float*)d_in[0];
    const int*   ei       = (const int*)d_in[1];
    const float* W1       = (const float*)d_in[3];
    const float* att_src1 = (const float*)d_in[4];
    const float* att_dst1 = (const float*)d_in[5];
    const float* bias1    = (const float*)d_in[6];
    const float* W_ih     = (const float*)d_in[7];
    const float* b_ih     = (const float*)d_in[9];
    const float* b_hh     = (const float*)d_in[10];
    const float* W2       = (const float*)d_in[11];
    const float* att_src2 = (const float*)d_in[12];
    const float* att_dst2 = (const float*)d_in[13];
    const float* bias2    = (const float*)d_in[14];
    float* out = (float*)d_out;

    int E = in_sizes[1] / 2;
    int etot = E + NN;

    void* p_deg = nullptr;   cudaGetSymbolAddress(&p_deg, g_deg);
    void* p_v1 = nullptr;    cudaGetSymbolAddress(&p_v1, g_v1);
    void* p_v2 = nullptr;    cudaGetSymbolAddress(&p_v2, g_v2);
    void* p_aggX = nullptr;  cudaGetSymbolAddress(&p_aggX, g_aggX);
    void* p_agg1 = nullptr;  cudaGetSymbolAddress(&p_agg1, g_agg1);
    void* p_aggC = nullptr;  cudaGetSymbolAddress(&p_aggC, g_aggC);
    void* p_gates = nullptr; cudaGetSymbolAddress(&p_gates, g_gates);
    void* p_pre = nullptr;   cudaGetSymbolAddress(&p_pre, g_pre);
    void* p_h2 = nullptr;    cudaGetSymbolAddress(&p_h2, g_h2);
    void* p_wiht = nullptr;  cudaGetSymbolAddress(&p_wiht, g_Wiht);

    // CSR build
    cudaMemsetAsync(p_deg, 0, NN * sizeof(int), 0);
    k_degree<<<(etot + 255) / 256, 256>>>(ei, E);
    k_scan<<<1, 1024>>>();
    k_scatter<<<(etot + 255) / 256, 256>>>(ei, E);

    // folds (exact fp32)
    k_transpose<<<(G4 * D1 + 255) / 256, 256>>>(W_ih);
    k_fold_attn<<<(FIN * 16 + 255) / 256, 256>>>(W1, att_src1, att_dst1, (float*)p_v1, FIN);
    k_fold_attn<<<(F2C * 16 + 255) / 256, 256>>>(W2, att_src2, att_dst2, (float*)p_v2, F2C);
    k_foldb<<<1, 256>>>(bias1, b_ih, b_hh);

    // ---- layer 1 ----
    k_attnx<FIN><<<2500, 256>>>(x, (const float*)p_v1);
    k_stats<<<(NN * HC + 255) / 256, 256>>>();
    k_gatherX<<<2500, 256>>>(x);
    {
        dim3 grid(1, (NN + 127) / 128, HC);
        k_tfgemm_h<FIN><<<grid, 256>>>(NN, (const float*)p_aggX, W1, (float*)p_agg1);
    }
    {
        dim3 grid(G4 / 128, (NN + 127) / 128);
        k_tfgemm<<<grid, 256>>>(NN, G4, D1, (const float*)p_agg1,
                                (const float*)p_wiht, (float*)p_gates);
    }
    k_lstm<<<(NN * F2C + 255) / 256, 256>>>();

    // ---- layer 2 ----
    k_attnx<F2C><<<2500, 256>>>((const float*)p_h2, (const float*)p_v2);
    k_stats<<<(NN * HC + 255) / 256, 256>>>();
    k_gatherH<<<2500, 256>>>();
    {
        dim3 grid(1, (NN + 127) / 128, HC);
        k_tfgemm_h<F2C><<<grid, 256>>>(NN, (const float*)p_aggC, W2, (float*)p_pre);
    }
    k_softmax<<<NN, 256>>>((const float*)p_pre, bias2, out);
}

// round 5
// speedup vs baseline: 1.3767x; 1.3767x over previous
#include <cuda_runtime.h>
#include <cuda_bf16.h>
#include <math.h>

#define NN 20000
#define EE 320000
#define ET (EE + NN)
#define FIN 128
#define F2C 64
#define HC 8
#define D1 512
#define G4 256

// ---------------- scratch ----------------------------------------------------
__device__ float g_v1[FIN * 16];       // folded attn vectors layer1 [k][16]
__device__ float g_v2[F2C * 16];       // folded attn vectors layer2 [k][16]
__device__ float g_Wiht[D1 * G4];      // W_ih transposed [512,256]
__device__ float g_h1[NN * D1];        // x @ W1
__device__ float g_agg1[NN * D1];      // GAT1 output (incl bias1)
__device__ float g_gates[NN * G4];
__device__ float g_h2[NN * F2C];
__device__ float g_aggC[NN * HC * F2C];// per-head gathered h2 [N,8,64]
__device__ float g_pre[NN * D1];       // pre-softmax (no bias2)
__device__ float g_as[NN * HC];
__device__ float g_ad[NN * HC];
__device__ float g_m[NN * HC];
__device__ float g_den[NN * HC];
__device__ int   g_deg[NN];
__device__ int   g_offs[NN + 1];
__device__ int   g_cur[NN];
__device__ int   g_csrc[ET];

__device__ __forceinline__ float sigf(float x) { return 1.0f / (1.0f + __expf(-x)); }
__device__ __forceinline__ unsigned f2tf(float f) {
    unsigned u;
    asm("cvt.rna.tf32.f32 %0, %1;" : "=r"(u) : "f"(f));
    return u;
}
__device__ __forceinline__ float lrelu(float e) { return (e > 0.f) ? e : 0.2f * e; }

// ---------------- CSR build (proven) ------------------------------------------
__global__ void k_degree(const int* __restrict__ ei, int E) {
    int i = blockIdx.x * blockDim.x + threadIdx.x;
    if (i >= E + NN) return;
    int dst = (i < E) ? ei[E + i] : (i - E);
    atomicAdd(&g_deg[dst], 1);
}

__global__ void k_scan() {
    __shared__ int sums[1024];
    const int CH = 20;
    int t = threadIdx.x;
    int b = t * CH;
    int e = min(b + CH, NN);
    int tmp[CH];
    int local = 0;
    for (int i = b; i < e; i++) { tmp[i - b] = g_deg[i]; local += tmp[i - b]; }
    sums[t] = local;
    __syncthreads();
    for (int o = 1; o < 1024; o <<= 1) {
        int v = (t >= o) ? sums[t - o] : 0;
        __syncthreads();
        sums[t] += v;
        __syncthreads();
    }
    int run = sums[t] - local;
    for (int i = b; i < e; i++) {
        g_offs[i] = run;
        g_cur[i]  = run;
        run += tmp[i - b];
    }
    if (b < NN && e == NN) g_offs[NN] = run;
}

__global__ void k_scatter(const int* __restrict__ ei, int E) {
    int i = blockIdx.x * blockDim.x + threadIdx.x;
    if (i >= E + NN) return;
    int src, dst;
    if (i < E) { src = ei[i]; dst = ei[E + i]; }
    else       { src = dst = i - E; }
    int pos = atomicAdd(&g_cur[dst], 1);
    g_csrc[pos] = src;
}

// ---------------- folds (exact fp32) ------------------------------------------
__global__ void k_transpose(const float* __restrict__ Wih) {
    int idx = blockIdx.x * blockDim.x + threadIdx.x;
    if (idx >= G4 * D1) return;
    int j = idx >> 9;
    int k = idx & 511;
    g_Wiht[k * G4 + j] = Wih[idx];
}

// V[k][col]: col<8 -> sum_f W[k, h*64+f]*att_src[h*64+f]; col>=8 -> att_dst
__global__ void k_fold_attn(const float* __restrict__ W, const float* __restrict__ asrc,
                            const float* __restrict__ adst, float* __restrict__ V, int K) {
    int idx = blockIdx.x * blockDim.x + threadIdx.x;
    if (idx >= K * 16) return;
    int k = idx >> 4;
    int col = idx & 15;
    int h = col & 7;
    const float* att = (col & 8) ? adst : asrc;
    float acc = 0.f;
#pragma unroll 8
    for (int f = 0; f < F2C; f++)
        acc += W[(long)k * D1 + h * F2C + f] * att[h * F2C + f];
    V[idx] = acc;
}

// ---------------- attention logits from input features ------------------------
template <int K>
__global__ __launch_bounds__(256) void k_attnx(const float* __restrict__ feat,
                                               const float* __restrict__ V) {
    __shared__ float sV[K * 17];
    int tid = threadIdx.x;
    for (int idx = tid; idx < K * 16; idx += 256) {
        int k = idx >> 4, c = idx & 15;
        sV[k * 17 + c] = V[idx];
    }
    __syncthreads();
    int warp = tid >> 5, lane = tid & 31;
    int n = blockIdx.x * 8 + warp;
    if (n >= NN) return;
    float xv[K / 32];
#pragma unroll
    for (int c = 0; c < K / 32; c++) xv[c] = feat[(long)n * K + c * 32 + lane];
    float acc[16];
#pragma unroll
    for (int h = 0; h < 16; h++) acc[h] = 0.f;
#pragma unroll
    for (int c = 0; c < K / 32; c++) {
        int k = c * 32 + lane;
#pragma unroll
        for (int h = 0; h < 16; h++) acc[h] += xv[c] * sV[k * 17 + h];
    }
#pragma unroll
    for (int off = 16; off > 0; off >>= 1)
#pragma unroll
        for (int h = 0; h < 16; h++)
            acc[h] += __shfl_xor_sync(0xffffffffu, acc[h], off);
    if (lane == 0) {
#pragma unroll
        for (int h = 0; h < 8; h++) {
            g_as[n * HC + h] = acc[h];
            g_ad[n * HC + h] = acc[8 + h];
        }
    }
}

// ---------------- per (node,head) online softmax stats -------------------------
__global__ void k_stats() {
    int idx = blockIdx.x * blockDim.x + threadIdx.x;
    if (idx >= NN * HC) return;
    int n = idx >> 3, h = idx & 7;
    float adn = g_ad[idx];
    int beg = g_offs[n], end = g_offs[n + 1];
    int src = g_csrc[beg];
    float e = lrelu(g_as[src * HC + h] + adn);
    float mx = e, s = 1.0f;
    for (int j = beg + 1; j < end; j++) {
        src = g_csrc[j];
        e = lrelu(g_as[src * HC + h] + adn);
        if (e > mx) { s *= __expf(mx - e); mx = e; }
        s += __expf(e - mx);
    }
    g_m[idx] = mx;
    g_den[idx] = s;
}

// ---------------- layer-1 aggregation (R2-proven, 2KB/edge, +bias, unroll2) ----
__global__ __launch_bounds__(128) void k_aggregate(const float* __restrict__ hsrc,
                                                   const float* __restrict__ bias,
                                                   float* __restrict__ out) {
    int n = blockIdx.x;
    int t = threadIdx.x;
    int h = t >> 4;
    float adn = g_ad[n * HC + h];
    float mn  = g_m[n * HC + h];
    float inv = 1.0f / (g_den[n * HC + h] + 1e-16f);
    int beg = g_offs[n], end = g_offs[n + 1];
    float4 acc = make_float4(0.f, 0.f, 0.f, 0.f);
    int j = beg;
    for (; j + 1 < end; j += 2) {
        int s0 = g_csrc[j];
        int s1 = g_csrc[j + 1];
        float e0 = lrelu(g_as[s0 * HC + h] + adn);
        float e1 = lrelu(g_as[s1 * HC + h] + adn);
        float a0 = __expf(e0 - mn) * inv;
        float a1 = __expf(e1 - mn) * inv;
        float4 v0 = *(const float4*)&hsrc[(long)s0 * D1 + t * 4];
        float4 v1 = *(const float4*)&hsrc[(long)s1 * D1 + t * 4];
        acc.x += a0 * v0.x + a1 * v1.x;
        acc.y += a0 * v0.y + a1 * v1.y;
        acc.z += a0 * v0.z + a1 * v1.z;
        acc.w += a0 * v0.w + a1 * v1.w;
    }
    if (j < end) {
        int s = g_csrc[j];
        float e = lrelu(g_as[s * HC + h] + adn);
        float alpha = __expf(e - mn) * inv;
        float4 v = *(const float4*)&hsrc[(long)s * D1 + t * 4];
        acc.x += alpha * v.x;
        acc.y += alpha * v.y;
        acc.z += alpha * v.z;
        acc.w += alpha * v.w;
    }
    float4 b = *(const float4*)&bias[t * 4];
    acc.x += b.x; acc.y += b.y; acc.z += b.z; acc.w += b.w;
    *(float4*)&out[(long)n * D1 + t * 4] = acc;
}

// ---------------- layer-2 per-head gather of h2 (256B/edge, unroll2) -----------
// warp per node; lane: head = lane>>2, quad q owns h2 feats [q*16, q*16+16)
__global__ __launch_bounds__(256) void k_gatherH() {
    int warp = threadIdx.x >> 5, lane = threadIdx.x & 31;
    int n = blockIdx.x * 8 + warp;
    if (n >= NN) return;
    int h = lane >> 2;
    int q = lane & 3;
    float adn = g_ad[n * HC + h];
    float mn  = g_m[n * HC + h];
    float inv = 1.0f / (g_den[n * HC + h] + 1e-16f);
    int beg = g_offs[n], end = g_offs[n + 1];
    float4 acc[4];
#pragma unroll
    for (int i = 0; i < 4; i++) acc[i] = make_float4(0.f, 0.f, 0.f, 0.f);
    int j = beg;
    for (; j + 1 < end; j += 2) {
        int s0 = g_csrc[j];
        int s1 = g_csrc[j + 1];
        float e0 = lrelu(g_as[s0 * HC + h] + adn);
        float e1 = lrelu(g_as[s1 * HC + h] + adn);
        float a0 = __expf(e0 - mn) * inv;
        float a1 = __expf(e1 - mn) * inv;
        const float4* p0 = (const float4*)&g_h2[(long)s0 * F2C + q * 16];
        const float4* p1 = (const float4*)&g_h2[(long)s1 * F2C + q * 16];
#pragma unroll
        for (int i = 0; i < 4; i++) {
            float4 v0 = p0[i];
            float4 v1 = p1[i];
            acc[i].x += a0 * v0.x + a1 * v1.x;
            acc[i].y += a0 * v0.y + a1 * v1.y;
            acc[i].z += a0 * v0.z + a1 * v1.z;
            acc[i].w += a0 * v0.w + a1 * v1.w;
        }
    }
    if (j < end) {
        int s = g_csrc[j];
        float e = lrelu(g_as[s * HC + h] + adn);
        float alpha = __expf(e - mn) * inv;
        const float4* p = (const float4*)&g_h2[(long)s * F2C + q * 16];
#pragma unroll
        for (int i = 0; i < 4; i++) {
            float4 v = p[i];
            acc[i].x += alpha * v.x;
            acc[i].y += alpha * v.y;
            acc[i].z += alpha * v.z;
            acc[i].w += alpha * v.w;
        }
    }
    float4* op = (float4*)&g_aggC[(long)n * (HC * F2C) + h * F2C + q * 16];
#pragma unroll
    for (int i = 0; i < 4; i++) op[i] = acc[i];
}

// ---------------- TF32 GEMM, 128x128 tile (proven) ------------------------------
__global__ __launch_bounds__(256) void k_tfgemm(int M, int N, int K,
                                                const float* __restrict__ A,
                                                const float* __restrict__ B,
                                                float* __restrict__ C) {
    __shared__ unsigned As[16][136];
    __shared__ unsigned Bs[16][136];
    int tid  = threadIdx.x;
    int lane = tid & 31;
    int warp = tid >> 5;
    int wr = warp & 3;
    int wc = warp >> 2;
    int blockRow = blockIdx.y * 128;
    int blockCol = blockIdx.x * 128;

    float acc[2][8][4];
#pragma unroll
    for (int i = 0; i < 2; i++)
#pragma unroll
        for (int j = 0; j < 8; j++)
#pragma unroll
            for (int q = 0; q < 4; q++) acc[i][j][q] = 0.0f;

    int arow = tid >> 2;
    int acol = (tid & 3) * 4;
    int brow = tid >> 5;
    int bcol = (tid & 31) * 4;

    for (int k0 = 0; k0 < K; k0 += 16) {
#pragma unroll
        for (int half = 0; half < 2; half++) {
            int r = arow + half * 64;
            float4 v = make_float4(0.f, 0.f, 0.f, 0.f);
            if (blockRow + r < M)
                v = *(const float4*)&A[(long)(blockRow + r) * K + k0 + acol];
            As[acol + 0][r] = f2tf(v.x);
            As[acol + 1][r] = f2tf(v.y);
            As[acol + 2][r] = f2tf(v.z);
            As[acol + 3][r] = f2tf(v.w);
        }
#pragma unroll
        for (int half = 0; half < 2; half++) {
            int kr = brow + half * 8;
            float4 v = *(const float4*)&B[(long)(k0 + kr) * N + blockCol + bcol];
            uint4 u = make_uint4(f2tf(v.x), f2tf(v.y), f2tf(v.z), f2tf(v.w));
            *(uint4*)&Bs[kr][bcol] = u;
        }
        __syncthreads();

#pragma unroll
        for (int ks = 0; ks < 16; ks += 8) {
            unsigned a[2][4], b[8][2];
            int r0 = wr * 32 + (lane >> 2);
            int c0 = ks + (lane & 3);
#pragma unroll
            for (int i = 0; i < 2; i++) {
                a[i][0] = As[c0][r0 + i * 16];
                a[i][1] = As[c0][r0 + i * 16 + 8];
                a[i][2] = As[c0 + 4][r0 + i * 16];
                a[i][3] = As[c0 + 4][r0 + i * 16 + 8];
            }
            int bn = wc * 64 + (lane >> 2);
#pragma unroll
            for (int j = 0; j < 8; j++) {
                b[j][0] = Bs[c0][bn + j * 8];
                b[j][1] = Bs[c0 + 4][bn + j * 8];
            }
#pragma unroll
            for (int i = 0; i < 2; i++) {
#pragma unroll
                for (int j = 0; j < 8; j++) {
                    asm volatile(
                        "mma.sync.aligned.m16n8k8.row.col.f32.tf32.tf32.f32 "
                        "{%0,%1,%2,%3}, {%4,%5,%6,%7}, {%8,%9}, {%0,%1,%2,%3};"
                        : "+f"(acc[i][j][0]), "+f"(acc[i][j][1]),
                          "+f"(acc[i][j][2]), "+f"(acc[i][j][3])
                        : "r"(a[i][0]), "r"(a[i][1]), "r"(a[i][2]), "r"(a[i][3]),
                          "r"(b[j][0]), "r"(b[j][1]));
                }
            }
        }
        __syncthreads();
    }

#pragma unroll
    for (int i = 0; i < 2; i++) {
        int r = blockRow + wr * 32 + i * 16 + (lane >> 2);
#pragma unroll
        for (int j = 0; j < 8; j++) {
            int c = blockCol + wc * 64 + j * 8 + (lane & 3) * 2;
            if (r < M)
                *(float2*)&C[(long)r * N + c] = make_float2(acc[i][j][0], acc[i][j][1]);
            if (r + 8 < M)
                *(float2*)&C[(long)(r + 8) * N + c] = make_float2(acc[i][j][2], acc[i][j][3]);
        }
    }
}

// ---------------- batched per-head TF32 GEMM, 128x64 tile, KD=64 ----------------
// C[r, h*64+c] = sum_k A[r, h*64+k] * B[k, h*64+c];  A:[M,512], B:[64,512], C:[M,512]
__global__ __launch_bounds__(256) void k_tfgemm_h64(int M,
                                                    const float* __restrict__ A,
                                                    const float* __restrict__ B,
                                                    float* __restrict__ C) {
    __shared__ unsigned As[16][136];
    __shared__ unsigned Bs[16][72];
    const int KD = 64;
    const int lda = 8 * KD;
    int h = blockIdx.z;
    const float* Ap = A + h * KD;
    const float* Bp = B + h * 64;
    float* Cp = C + h * 64;
    int tid  = threadIdx.x;
    int lane = tid & 31;
    int warp = tid >> 5;
    int wr = warp & 3;
    int wc = warp >> 2;
    int blockRow = blockIdx.y * 128;

    float acc[2][4][4];
#pragma unroll
    for (int i = 0; i < 2; i++)
#pragma unroll
        for (int j = 0; j < 4; j++)
#pragma unroll
            for (int q = 0; q < 4; q++) acc[i][j][q] = 0.0f;

    int arow = tid >> 2;
    int acol = (tid & 3) * 4;
    int brow = tid >> 4;
    int bcol = (tid & 15) * 4;

    for (int k0 = 0; k0 < KD; k0 += 16) {
#pragma unroll
        for (int half = 0; half < 2; half++) {
            int r = arow + half * 64;
            float4 v = make_float4(0.f, 0.f, 0.f, 0.f);
            if (blockRow + r < M)
                v = *(const float4*)&Ap[(long)(blockRow + r) * lda + k0 + acol];
            As[acol + 0][r] = f2tf(v.x);
            As[acol + 1][r] = f2tf(v.y);
            As[acol + 2][r] = f2tf(v.z);
            As[acol + 3][r] = f2tf(v.w);
        }
        {
            float4 v = *(const float4*)&Bp[(long)(k0 + brow) * D1 + bcol];
            Bs[brow][bcol + 0] = f2tf(v.x);
            Bs[brow][bcol + 1] = f2tf(v.y);
            Bs[brow][bcol + 2] = f2tf(v.z);
            Bs[brow][bcol + 3] = f2tf(v.w);
        }
        __syncthreads();

#pragma unroll
        for (int ks = 0; ks < 16; ks += 8) {
            unsigned a[2][4], b[4][2];
            int r0 = wr * 32 + (lane >> 2);
            int c0 = ks + (lane & 3);
#pragma unroll
            for (int i = 0; i < 2; i++) {
                a[i][0] = As[c0][r0 + i * 16];
                a[i][1] = As[c0][r0 + i * 16 + 8];
                a[i][2] = As[c0 + 4][r0 + i * 16];
                a[i][3] = As[c0 + 4][r0 + i * 16 + 8];
            }
            int bn = wc * 32 + (lane >> 2);
#pragma unroll
            for (int j = 0; j < 4; j++) {
                b[j][0] = Bs[c0][bn + j * 8];
                b[j][1] = Bs[c0 + 4][bn + j * 8];
            }
#pragma unroll
            for (int i = 0; i < 2; i++) {
#pragma unroll
                for (int j = 0; j < 4; j++) {
                    asm volatile(
                        "mma.sync.aligned.m16n8k8.row.col.f32.tf32.tf32.f32 "
                        "{%0,%1,%2,%3}, {%4,%5,%6,%7}, {%8,%9}, {%0,%1,%2,%3};"
                        : "+f"(acc[i][j][0]), "+f"(acc[i][j][1]),
                          "+f"(acc[i][j][2]), "+f"(acc[i][j][3])
                        : "r"(a[i][0]), "r"(a[i][1]), "r"(a[i][2]), "r"(a[i][3]),
                          "r"(b[j][0]), "r"(b[j][1]));
                }
            }
        }
        __syncthreads();
    }

#pragma unroll
    for (int i = 0; i < 2; i++) {
        int r = blockRow + wr * 32 + i * 16 + (lane >> 2);
#pragma unroll
        for (int j = 0; j < 4; j++) {
            int c = wc * 32 + j * 8 + (lane & 3) * 2;
            if (r < M)
                *(float2*)&Cp[(long)r * D1 + c] = make_float2(acc[i][j][0], acc[i][j][1]);
            if (r + 8 < M)
                *(float2*)&Cp[(long)(r + 8) * D1 + c] = make_float2(acc[i][j][2], acc[i][j][3]);
        }
    }
}

// ---------------- LSTM elementwise + relu ---------------------------------------
__global__ void k_lstm(const float* __restrict__ b_ih, const float* __restrict__ b_hh) {
    int idx = blockIdx.x * blockDim.x + threadIdx.x;
    if (idx >= NN * F2C) return;
    int n = idx >> 6, j = idx & 63;
    const float* g = g_gates + (long)n * G4;
    float i_ = g[j]       + b_ih[j]       + b_hh[j];
    float gg = g[128 + j] + b_ih[128 + j] + b_hh[128 + j];
    float o_ = g[192 + j] + b_ih[192 + j] + b_hh[192 + j];
    float c  = sigf(i_) * tanhf(gg);
    float hh = sigf(o_) * tanhf(c);
    g_h2[idx] = fmaxf(hh, 0.0f);
}

// ---------------- bias2 + row softmax over 512 ----------------------------------
__global__ __launch_bounds__(256) void k_softmax(const float* __restrict__ in,
                                                 const float* __restrict__ bias2,
                                                 float* __restrict__ out) {
    __shared__ float red[256];
    int n = blockIdx.x, t = threadIdx.x;
    float a = in[(long)n * D1 + t] + bias2[t];
    float b = in[(long)n * D1 + 256 + t] + bias2[256 + t];
    red[t] = fmaxf(a, b);
    __syncthreads();
#pragma unroll
    for (int o = 128; o > 0; o >>= 1) {
        if (t < o) red[t] = fmaxf(red[t], red[t + o]);
        __syncthreads();
    }
    float mx = red[0];
    __syncthreads();
    float ea = __expf(a - mx), eb = __expf(b - mx);
    red[t] = ea + eb;
    __syncthreads();
#pragma unroll
    for (int o = 128; o > 0; o >>= 1) {
        if (t < o) red[t] += red[t + o];
        __syncthreads();
    }
    float inv = 1.0f / red[0];
    out[(long)n * D1 + t] = ea * inv;
    out[(long)n * D1 + 256 + t] = eb * inv;
}

// ---------------- launch ----------------------------------------------------------
extern "C" void kernel_launch(void* const* d_in, const int* in_sizes, int n_in,
                              void* d_out, int out_size) {
    const float* x        = (const float*)d_in[0];
    const int*   ei       = (const int*)d_in[1];
    const float* W1       = (const float*)d_in[3];
    const float* att_src1 = (const float*)d_in[4];
    const float* att_dst1 = (const float*)d_in[5];
    const float* bias1    = (const float*)d_in[6];
    const float* W_ih     = (const float*)d_in[7];
    const float* b_ih     = (const float*)d_in[9];
    const float* b_hh     = (const float*)d_in[10];
    const float* W2       = (const float*)d_in[11];
    const float* att_src2 = (const float*)d_in[12];
    const float* att_dst2 = (const float*)d_in[13];
    const float* bias2    = (const float*)d_in[14];
    float* out = (float*)d_out;

    int E = in_sizes[1] / 2;
    int etot = E + NN;

    void* p_deg = nullptr;   cudaGetSymbolAddress(&p_deg, g_deg);
    void* p_v1 = nullptr;    cudaGetSymbolAddress(&p_v1, g_v1);
    void* p_v2 = nullptr;    cudaGetSymbolAddress(&p_v2, g_v2);
    void* p_h1 = nullptr;    cudaGetSymbolAddress(&p_h1, g_h1);
    void* p_agg1 = nullptr;  cudaGetSymbolAddress(&p_agg1, g_agg1);
    void* p_aggC = nullptr;  cudaGetSymbolAddress(&p_aggC, g_aggC);
    void* p_gates = nullptr; cudaGetSymbolAddress(&p_gates, g_gates);
    void* p_pre = nullptr;   cudaGetSymbolAddress(&p_pre, g_pre);
    void* p_h2 = nullptr;    cudaGetSymbolAddress(&p_h2, g_h2);
    void* p_wiht = nullptr;  cudaGetSymbolAddress(&p_wiht, g_Wiht);

    // CSR build
    cudaMemsetAsync(p_deg, 0, NN * sizeof(int), 0);
    k_degree<<<(etot + 255) / 256, 256>>>(ei, E);
    k_scan<<<1, 1024>>>();
    k_scatter<<<(etot + 255) / 256, 256>>>(ei, E);

    // folds
    k_transpose<<<(G4 * D1 + 255) / 256, 256>>>(W_ih);
    k_fold_attn<<<(FIN * 16 + 255) / 256, 256>>>(W1, att_src1, att_dst1, (float*)p_v1, FIN);
    k_fold_attn<<<(F2C * 16 + 255) / 256, 256>>>(W2, att_src2, att_dst2, (float*)p_v2, F2C);

    // ---- layer 1 (R2-proven path) ----
    {
        dim3 grid(D1 / 128, (NN + 127) / 128);
        k_tfgemm<<<grid, 256>>>(NN, D1, FIN, x, W1, (float*)p_h1);
    }
    k_attnx<FIN><<<2500, 256>>>(x, (const float*)p_v1);
    k_stats<<<(NN * HC + 255) / 256, 256>>>();
    k_aggregate<<<NN, 128>>>((const float*)p_h1, bias1, (float*)p_agg1);
    {
        dim3 grid(G4 / 128, (NN + 127) / 128);
        k_tfgemm<<<grid, 256>>>(NN, G4, D1, (const float*)p_agg1,
                                (const float*)p_wiht, (float*)p_gates);
    }
    k_lstm<<<(NN * F2C + 255) / 256, 256>>>(b_ih, b_hh);

    // ---- layer 2 (restructured: narrow gather + per-head GEMM) ----
    k_attnx<F2C><<<2500, 256>>>((const float*)p_h2, (const float*)p_v2);
    k_stats<<<(NN * HC + 255) / 256, 256>>>();
    k_gatherH<<<2500, 256>>>();
    {
        dim3 grid(1, (NN + 127) / 128, HC);
        k_tfgemm_h64<<<grid, 256>>>(NN, (const float*)p_aggC, W2, (float*)p_pre);
    }
    k_softmax<<<NN, 256>>>((const float*)p_pre, bias2, out);
}

// round 6
// speedup vs baseline: 1.4809x; 1.0757x over previous
#include <cuda_runtime.h>
#include <cuda_bf16.h>
#include <math.h>

#define NN 20000
#define EE 320000
#define ET (EE + NN)
#define FIN 128
#define F2C 64
#define HC 8
#define D1 512
#define G4 256

// ---------------- scratch ----------------------------------------------------
__device__ float g_v1[FIN * 16];            // folded attn vectors layer1
__device__ float g_v2[F2C * 16];            // folded attn vectors layer2
__device__ float g_Wiht[D1 * G4];           // W_ih^T [512,256]
__device__ __nv_bfloat16 g_h1b[NN * D1];    // x @ W1 (bf16, gather source)
__device__ float g_agg1[NN * D1];           // GAT1 output (incl bias1)
__device__ float g_gates[NN * G4];
__device__ float g_h2[NN * F2C];
__device__ __nv_bfloat16 g_h3b[NN * D1];    // h2 @ W2 (bf16, gather source)
__device__ float g_pre[NN * D1];            // pre-softmax (incl bias2)
__device__ float g_as[NN * HC];
__device__ float g_ad[NN * HC];
__device__ float g_m[NN * HC];
__device__ float g_den[NN * HC];
__device__ int   g_deg[NN];
__device__ int   g_offs[NN + 1];
__device__ int   g_cur[NN];
__device__ int   g_csrc[ET];

__device__ __forceinline__ float sigf(float x) { return 1.0f / (1.0f + __expf(-x)); }
__device__ __forceinline__ float lrelu(float e) { return (e > 0.f) ? e : 0.2f * e; }

// ---------------- CSR build (proven) ------------------------------------------
__global__ void k_degree(const int* __restrict__ ei, int E) {
    int i = blockIdx.x * blockDim.x + threadIdx.x;
    if (i >= E + NN) return;
    int dst = (i < E) ? ei[E + i] : (i - E);
    atomicAdd(&g_deg[dst], 1);
}

__global__ void k_scan() {
    __shared__ int sums[1024];
    const int CH = 20;
    int t = threadIdx.x;
    int b = t * CH;
    int e = min(b + CH, NN);
    int tmp[CH];
    int local = 0;
    for (int i = b; i < e; i++) { tmp[i - b] = g_deg[i]; local += tmp[i - b]; }
    sums[t] = local;
    __syncthreads();
    for (int o = 1; o < 1024; o <<= 1) {
        int v = (t >= o) ? sums[t - o] : 0;
        __syncthreads();
        sums[t] += v;
        __syncthreads();
    }
    int run = sums[t] - local;
    for (int i = b; i < e; i++) {
        g_offs[i] = run;
        g_cur[i]  = run;
        run += tmp[i - b];
    }
    if (b < NN && e == NN) g_offs[NN] = run;
}

__global__ void k_scatter(const int* __restrict__ ei, int E) {
    int i = blockIdx.x * blockDim.x + threadIdx.x;
    if (i >= E + NN) return;
    int src, dst;
    if (i < E) { src = ei[i]; dst = ei[E + i]; }
    else       { src = dst = i - E; }
    int pos = atomicAdd(&g_cur[dst], 1);
    g_csrc[pos] = src;
}

// ---------------- folds (exact fp32) ------------------------------------------
__global__ void k_transpose(const float* __restrict__ Wih) {
    int idx = blockIdx.x * blockDim.x + threadIdx.x;
    if (idx >= G4 * D1) return;
    int j = idx >> 9;
    int k = idx & 511;
    g_Wiht[k * G4 + j] = Wih[idx];
}

__global__ void k_fold_attn(const float* __restrict__ W, const float* __restrict__ asrc,
                            const float* __restrict__ adst, float* __restrict__ V, int K) {
    int idx = blockIdx.x * blockDim.x + threadIdx.x;
    if (idx >= K * 16) return;
    int k = idx >> 4;
    int col = idx & 15;
    int h = col & 7;
    const float* att = (col & 8) ? adst : asrc;
    float acc = 0.f;
#pragma unroll 8
    for (int f = 0; f < F2C; f++)
        acc += W[(long)k * D1 + h * F2C + f] * att[h * F2C + f];
    V[idx] = acc;
}

// ---------------- attention logits from input features --------------------------
template <int K>
__global__ __launch_bounds__(256) void k_attnx(const float* __restrict__ feat,
                                               const float* __restrict__ V) {
    __shared__ float sV[K * 17];
    int tid = threadIdx.x;
    for (int idx = tid; idx < K * 16; idx += 256) {
        int k = idx >> 4, c = idx & 15;
        sV[k * 17 + c] = V[idx];
    }
    __syncthreads();
    int warp = tid >> 5, lane = tid & 31;
    int n = blockIdx.x * 8 + warp;
    if (n >= NN) return;
    float xv[K / 32];
#pragma unroll
    for (int c = 0; c < K / 32; c++) xv[c] = feat[(long)n * K + c * 32 + lane];
    float acc[16];
#pragma unroll
    for (int h = 0; h < 16; h++) acc[h] = 0.f;
#pragma unroll
    for (int c = 0; c < K / 32; c++) {
        int k = c * 32 + lane;
#pragma unroll
        for (int h = 0; h < 16; h++) acc[h] += xv[c] * sV[k * 17 + h];
    }
#pragma unroll
    for (int off = 16; off > 0; off >>= 1)
#pragma unroll
        for (int h = 0; h < 16; h++)
            acc[h] += __shfl_xor_sync(0xffffffffu, acc[h], off);
    if (lane == 0) {
#pragma unroll
        for (int h = 0; h < 8; h++) {
            g_as[n * HC + h] = acc[h];
            g_ad[n * HC + h] = acc[8 + h];
        }
    }
}

// ---------------- per (node,head) online softmax stats ---------------------------
__global__ void k_stats() {
    int idx = blockIdx.x * blockDim.x + threadIdx.x;
    if (idx >= NN * HC) return;
    int n = idx >> 3, h = idx & 7;
    float adn = g_ad[idx];
    int beg = g_offs[n], end = g_offs[n + 1];
    int src = g_csrc[beg];
    float e = lrelu(g_as[src * HC + h] + adn);
    float mx = e, s = 1.0f;
    for (int j = beg + 1; j < end; j++) {
        src = g_csrc[j];
        e = lrelu(g_as[src * HC + h] + adn);
        if (e > mx) { s *= __expf(mx - e); mx = e; }
        s += __expf(e - mx);
    }
    g_m[idx] = mx;
    g_den[idx] = s;
}

// ---------------- aggregation from bf16 source (1KB/edge) -----------------------
// block = 128 thr per node; thread t owns 4 feats (2 bf16x2); head = t>>4
__global__ __launch_bounds__(128) void k_agg_bf16(const __nv_bfloat16* __restrict__ hsrc,
                                                  const float* __restrict__ bias,
                                                  float* __restrict__ out) {
    int n = blockIdx.x;
    int t = threadIdx.x;
    int h = t >> 4;
    float adn = g_ad[n * HC + h];
    float mn  = g_m[n * HC + h];
    float inv = 1.0f / (g_den[n * HC + h] + 1e-16f);
    int beg = g_offs[n], end = g_offs[n + 1];
    float4 acc = make_float4(0.f, 0.f, 0.f, 0.f);
    int j = beg;
    for (; j + 1 < end; j += 2) {
        int s0 = g_csrc[j];
        int s1 = g_csrc[j + 1];
        float e0 = lrelu(g_as[s0 * HC + h] + adn);
        float e1 = lrelu(g_as[s1 * HC + h] + adn);
        float a0 = __expf(e0 - mn) * inv;
        float a1 = __expf(e1 - mn) * inv;
        uint2 u0 = *(const uint2*)&hsrc[(long)s0 * D1 + t * 4];
        uint2 u1 = *(const uint2*)&hsrc[(long)s1 * D1 + t * 4];
        float2 p0 = __bfloat1622float2(*(__nv_bfloat162*)&u0.x);
        float2 p1 = __bfloat1622float2(*(__nv_bfloat162*)&u0.y);
        float2 q0 = __bfloat1622float2(*(__nv_bfloat162*)&u1.x);
        float2 q1 = __bfloat1622float2(*(__nv_bfloat162*)&u1.y);
        acc.x += a0 * p0.x + a1 * q0.x;
        acc.y += a0 * p0.y + a1 * q0.y;
        acc.z += a0 * p1.x + a1 * q1.x;
        acc.w += a0 * p1.y + a1 * q1.y;
    }
    if (j < end) {
        int s = g_csrc[j];
        float e = lrelu(g_as[s * HC + h] + adn);
        float a0 = __expf(e - mn) * inv;
        uint2 u0 = *(const uint2*)&hsrc[(long)s * D1 + t * 4];
        float2 p0 = __bfloat1622float2(*(__nv_bfloat162*)&u0.x);
        float2 p1 = __bfloat1622float2(*(__nv_bfloat162*)&u0.y);
        acc.x += a0 * p0.x;
        acc.y += a0 * p0.y;
        acc.z += a0 * p1.x;
        acc.w += a0 * p1.y;
    }
    float4 b = *(const float4*)&bias[t * 4];
    acc.x += b.x; acc.y += b.y; acc.z += b.z; acc.w += b.w;
    *(float4*)&out[(long)n * D1 + t * 4] = acc;
}

// ---------------- TF32 GEMM, 128x128 tile, reg-prefetch pipeline ----------------
// C store type templated: float (fp32) or __nv_bfloat16.
template <typename TO>
__device__ __forceinline__ void storeC2(TO* C, long idx, float a, float b);
template <>
__device__ __forceinline__ void storeC2<float>(float* C, long idx, float a, float b) {
    *(float2*)&C[idx] = make_float2(a, b);
}
template <>
__device__ __forceinline__ void storeC2<__nv_bfloat16>(__nv_bfloat16* C, long idx, float a, float b) {
    *(__nv_bfloat162*)&C[idx] = __floats2bfloat162_rn(a, b);
}

template <typename TO>
__global__ __launch_bounds__(256) void k_tfgemm(int M, int N, int K,
                                                const float* __restrict__ A,
                                                const float* __restrict__ B,
                                                TO* __restrict__ C) {
    __shared__ unsigned As[16][136];
    __shared__ unsigned Bs[16][136];
    int tid  = threadIdx.x;
    int lane = tid & 31;
    int warp = tid >> 5;
    int wr = warp & 3;
    int wc = warp >> 2;
    int blockRow = blockIdx.y * 128;
    int blockCol = blockIdx.x * 128;

    float acc[2][8][4];
#pragma unroll
    for (int i = 0; i < 2; i++)
#pragma unroll
        for (int j = 0; j < 8; j++)
#pragma unroll
            for (int q = 0; q < 4; q++) acc[i][j][q] = 0.0f;

    int arow = tid >> 2;
    int acol = (tid & 3) * 4;
    int brow = tid >> 5;
    int bcol = (tid & 31) * 4;

    // prologue: prefetch k0 = 0 into registers
    float4 aReg[2], bReg[2];
#pragma unroll
    for (int half = 0; half < 2; half++) {
        int r = arow + half * 64;
        aReg[half] = make_float4(0.f, 0.f, 0.f, 0.f);
        if (blockRow + r < M)
            aReg[half] = *(const float4*)&A[(long)(blockRow + r) * K + acol];
        bReg[half] = *(const float4*)&B[(long)(brow + half * 8) * N + blockCol + bcol];
    }

    for (int k0 = 0; k0 < K; k0 += 16) {
        // stage registers -> smem (raw fp32 bits; hw truncates to tf32)
#pragma unroll
        for (int half = 0; half < 2; half++) {
            int r = arow + half * 64;
            As[acol + 0][r] = __float_as_uint(aReg[half].x);
            As[acol + 1][r] = __float_as_uint(aReg[half].y);
            As[acol + 2][r] = __float_as_uint(aReg[half].z);
            As[acol + 3][r] = __float_as_uint(aReg[half].w);
            int kr = brow + half * 8;
            uint4 u = make_uint4(__float_as_uint(bReg[half].x), __float_as_uint(bReg[half].y),
                                 __float_as_uint(bReg[half].z), __float_as_uint(bReg[half].w));
            *(uint4*)&Bs[kr][bcol] = u;
        }
        __syncthreads();

        // prefetch next k-tile while mma consumes the current one
        if (k0 + 16 < K) {
#pragma unroll
            for (int half = 0; half < 2; half++) {
                int r = arow + half * 64;
                aReg[half] = make_float4(0.f, 0.f, 0.f, 0.f);
                if (blockRow + r < M)
                    aReg[half] = *(const float4*)&A[(long)(blockRow + r) * K + k0 + 16 + acol];
                bReg[half] = *(const float4*)&B[(long)(k0 + 16 + brow + half * 8) * N + blockCol + bcol];
            }
        }

#pragma unroll
        for (int ks = 0; ks < 16; ks += 8) {
            unsigned a[2][4], b[8][2];
            int r0 = wr * 32 + (lane >> 2);
            int c0 = ks + (lane & 3);
#pragma unroll
            for (int i = 0; i < 2; i++) {
                a[i][0] = As[c0][r0 + i * 16];
                a[i][1] = As[c0][r0 + i * 16 + 8];
                a[i][2] = As[c0 + 4][r0 + i * 16];
                a[i][3] = As[c0 + 4][r0 + i * 16 + 8];
            }
            int bn = wc * 64 + (lane >> 2);
#pragma unroll
            for (int j = 0; j < 8; j++) {
                b[j][0] = Bs[c0][bn + j * 8];
                b[j][1] = Bs[c0 + 4][bn + j * 8];
            }
#pragma unroll
            for (int i = 0; i < 2; i++) {
#pragma unroll
                for (int j = 0; j < 8; j++) {
                    asm volatile(
                        "mma.sync.aligned.m16n8k8.row.col.f32.tf32.tf32.f32 "
                        "{%0,%1,%2,%3}, {%4,%5,%6,%7}, {%8,%9}, {%0,%1,%2,%3};"
                        : "+f"(acc[i][j][0]), "+f"(acc[i][j][1]),
                          "+f"(acc[i][j][2]), "+f"(acc[i][j][3])
                        : "r"(a[i][0]), "r"(a[i][1]), "r"(a[i][2]), "r"(a[i][3]),
                          "r"(b[j][0]), "r"(b[j][1]));
                }
            }
        }
        __syncthreads();
    }

#pragma unroll
    for (int i = 0; i < 2; i++) {
        int r = blockRow + wr * 32 + i * 16 + (lane >> 2);
#pragma unroll
        for (int j = 0; j < 8; j++) {
            int c = blockCol + wc * 64 + j * 8 + (lane & 3) * 2;
            if (r < M)
                storeC2<TO>(C, (long)r * N + c, acc[i][j][0], acc[i][j][1]);
            if (r + 8 < M)
                storeC2<TO>(C, (long)(r + 8) * N + c, acc[i][j][2], acc[i][j][3]);
        }
    }
}

// ---------------- LSTM elementwise + relu ----------------------------------------
__global__ void k_lstm(const float* __restrict__ b_ih, const float* __restrict__ b_hh) {
    int idx = blockIdx.x * blockDim.x + threadIdx.x;
    if (idx >= NN * F2C) return;
    int n = idx >> 6, j = idx & 63;
    const float* g = g_gates + (long)n * G4;
    float i_ = g[j]       + b_ih[j]       + b_hh[j];
    float gg = g[128 + j] + b_ih[128 + j] + b_hh[128 + j];
    float o_ = g[192 + j] + b_ih[192 + j] + b_hh[192 + j];
    float c  = sigf(i_) * tanhf(gg);
    float hh = sigf(o_) * tanhf(c);
    g_h2[idx] = fmaxf(hh, 0.0f);
}

// ---------------- row softmax over 512 --------------------------------------------
__global__ __launch_bounds__(256) void k_softmax(const float* __restrict__ in,
                                                 float* __restrict__ out) {
    __shared__ float red[256];
    int n = blockIdx.x, t = threadIdx.x;
    float a = in[(long)n * D1 + t];
    float b = in[(long)n * D1 + 256 + t];
    red[t] = fmaxf(a, b);
    __syncthreads();
#pragma unroll
    for (int o = 128; o > 0; o >>= 1) {
        if (t < o) red[t] = fmaxf(red[t], red[t + o]);
        __syncthreads();
    }
    float mx = red[0];
    __syncthreads();
    float ea = __expf(a - mx), eb = __expf(b - mx);
    red[t] = ea + eb;
    __syncthreads();
#pragma unroll
    for (int o = 128; o > 0; o >>= 1) {
        if (t < o) red[t] += red[t + o];
        __syncthreads();
    }
    float inv = 1.0f / red[0];
    out[(long)n * D1 + t] = ea * inv;
    out[(long)n * D1 + 256 + t] = eb * inv;
}

// ---------------- launch ------------------------------------------------------------
extern "C" void kernel_launch(void* const* d_in, const int* in_sizes, int n_in,
                              void* d_out, int out_size) {
    const float* x        = (const float*)d_in[0];
    const int*   ei       = (const int*)d_in[1];
    const float* W1       = (const float*)d_in[3];
    const float* att_src1 = (const float*)d_in[4];
    const float* att_dst1 = (const float*)d_in[5];
    const float* bias1    = (const float*)d_in[6];
    const float* W_ih     = (const float*)d_in[7];
    const float* b_ih     = (const float*)d_in[9];
    const float* b_hh     = (const float*)d_in[10];
    const float* W2       = (const float*)d_in[11];
    const float* att_src2 = (const float*)d_in[12];
    const float* att_dst2 = (const float*)d_in[13];
    const float* bias2    = (const float*)d_in[14];
    float* out = (float*)d_out;

    int E = in_sizes[1] / 2;
    int etot = E + NN;

    void* p_deg = nullptr;   cudaGetSymbolAddress(&p_deg, g_deg);
    void* p_v1 = nullptr;    cudaGetSymbolAddress(&p_v1, g_v1);
    void* p_v2 = nullptr;    cudaGetSymbolAddress(&p_v2, g_v2);
    void* p_h1b = nullptr;   cudaGetSymbolAddress(&p_h1b, g_h1b);
    void* p_agg1 = nullptr;  cudaGetSymbolAddress(&p_agg1, g_agg1);
    void* p_gates = nullptr; cudaGetSymbolAddress(&p_gates, g_gates);
    void* p_pre = nullptr;   cudaGetSymbolAddress(&p_pre, g_pre);
    void* p_h2 = nullptr;    cudaGetSymbolAddress(&p_h2, g_h2);
    void* p_h3b = nullptr;   cudaGetSymbolAddress(&p_h3b, g_h3b);
    void* p_wiht = nullptr;  cudaGetSymbolAddress(&p_wiht, g_Wiht);

    // CSR build (launches 1-4, counting the memset)
    cudaMemsetAsync(p_deg, 0, NN * sizeof(int), 0);
    k_degree<<<(etot + 255) / 256, 256>>>(ei, E);
    k_scan<<<1, 1024>>>();
    k_scatter<<<(etot + 255) / 256, 256>>>(ei, E);

    // GEMM1 as launch #5 so ncu (-s 5 -c 1) profiles it: h1b = x @ W1 (bf16 out)
    {
        dim3 grid(D1 / 128, (NN + 127) / 128);
        k_tfgemm<__nv_bfloat16><<<grid, 256>>>(NN, D1, FIN, x, W1, (__nv_bfloat16*)p_h1b);
    }

    // folds
    k_transpose<<<(G4 * D1 + 255) / 256, 256>>>(W_ih);
    k_fold_attn<<<(FIN * 16 + 255) / 256, 256>>>(W1, att_src1, att_dst1, (float*)p_v1, FIN);
    k_fold_attn<<<(F2C * 16 + 255) / 256, 256>>>(W2, att_src2, att_dst2, (float*)p_v2, F2C);

    // ---- layer 1 ----
    k_attnx<FIN><<<2500, 256>>>(x, (const float*)p_v1);
    k_stats<<<(NN * HC + 255) / 256, 256>>>();
    k_agg_bf16<<<NN, 128>>>((const __nv_bfloat16*)p_h1b, bias1, (float*)p_agg1);
    {
        dim3 grid(G4 / 128, (NN + 127) / 128);
        k_tfgemm<float><<<grid, 256>>>(NN, G4, D1, (const float*)p_agg1,
                                       (const float*)p_wiht, (float*)p_gates);
    }
    k_lstm<<<(NN * F2C + 255) / 256, 256>>>(b_ih, b_hh);

    // ---- layer 2 ----
    {
        dim3 grid(D1 / 128, (NN + 127) / 128);
        k_tfgemm<__nv_bfloat16><<<grid, 256>>>(NN, D1, F2C, (const float*)p_h2, W2,
                                               (__nv_bfloat16*)p_h3b);
    }
    k_attnx<F2C><<<2500, 256>>>((const float*)p_h2, (const float*)p_v2);
    k_stats<<<(NN * HC + 255) / 256, 256>>>();
    k_agg_bf16<<<NN, 128>>>((const __nv_bfloat16*)p_h3b, bias2, (float*)p_pre);
    k_softmax<<<NN, 256>>>((const float*)p_pre, out);
}

// round 7
// speedup vs baseline: 1.6286x; 1.0997x over previous
#include <cuda_runtime.h>
#include <cuda_bf16.h>
#include <math.h>

#define NN 20000
#define EE 320000
#define ET (EE + NN)
#define FIN 128
#define F2C 64
#define HC 8
#define D1 512
#define G4 256

// ---------------- scratch ----------------------------------------------------
__device__ float g_v1[FIN * 16];
__device__ float g_v2[F2C * 16];
__device__ __nv_bfloat16 g_xb[NN * FIN];     // x bf16
__device__ __nv_bfloat16 g_W1b[D1 * FIN];    // W1^T bf16 [512,128]
__device__ __nv_bfloat16 g_Wihb[G4 * D1];    // W_ih bf16 [256,512] (already B^T)
__device__ __nv_bfloat16 g_W2b[D1 * F2C];    // W2^T bf16 [512,64]
__device__ __nv_bfloat16 g_h1b[NN * D1];     // GEMM1 out (gather source)
__device__ __nv_bfloat16 g_agg1b[NN * D1];   // GAT1 out (bf16, feeds GEMM2)
__device__ float g_gates[NN * G4];
__device__ float g_h2[NN * F2C];             // fp32 (attn logits)
__device__ __nv_bfloat16 g_h2b[NN * F2C];    // bf16 (GEMM3 A)
__device__ __nv_bfloat16 g_h3b[NN * D1];     // GEMM3 out (gather source)
__device__ float g_pre[NN * D1];             // pre-softmax fp32
__device__ float g_as[NN * HC];
__device__ float g_ad[NN * HC];
__device__ float g_m[NN * HC];
__device__ float g_den[NN * HC];
__device__ int   g_deg[NN];
__device__ int   g_offs[NN + 1];
__device__ int   g_cur[NN];
__device__ int   g_csrc[ET];

__device__ __forceinline__ float sigf(float x) { return 1.0f / (1.0f + __expf(-x)); }
__device__ __forceinline__ float lrelu(float e) { return (e > 0.f) ? e : 0.2f * e; }
__device__ __forceinline__ unsigned packbf(float a, float b) {
    __nv_bfloat162 t = __floats2bfloat162_rn(a, b);
    return *(unsigned*)&t;
}

// ---------------- CSR build ----------------------------------------------------
__global__ void k_degree(const int* __restrict__ ei, int E) {
    int i = blockIdx.x * blockDim.x + threadIdx.x;
    if (i >= E + NN) return;
    int dst = (i < E) ? ei[E + i] : (i - E);
    atomicAdd(&g_deg[dst], 1);
}

__global__ void k_scan() {
    __shared__ int sums[1024];
    const int CH = 20;
    int t = threadIdx.x;
    int b = t * CH;
    int e = min(b + CH, NN);
    int tmp[CH];
    int local = 0;
    for (int i = b; i < e; i++) { tmp[i - b] = g_deg[i]; local += tmp[i - b]; }
    sums[t] = local;
    __syncthreads();
    for (int o = 1; o < 1024; o <<= 1) {
        int v = (t >= o) ? sums[t - o] : 0;
        __syncthreads();
        sums[t] += v;
        __syncthreads();
    }
    int run = sums[t] - local;
    for (int i = b; i < e; i++) {
        g_offs[i] = run;
        g_cur[i]  = run;
        run += tmp[i - b];
    }
    if (b < NN && e == NN) g_offs[NN] = run;
}

__global__ void k_scatter(const int* __restrict__ ei, int E) {
    int i = blockIdx.x * blockDim.x + threadIdx.x;
    if (i >= E + NN) return;
    int src, dst;
    if (i < E) { src = ei[i]; dst = ei[E + i]; }
    else       { src = dst = i - E; }
    int pos = atomicAdd(&g_cur[dst], 1);
    g_csrc[pos] = src;
}

// ---------------- conversions ----------------------------------------------------
// straight fp32 -> bf16 (vector4); n multiple of 4
__global__ void k_cvt(const float* __restrict__ in, __nv_bfloat16* __restrict__ out, int n4) {
    int i = blockIdx.x * blockDim.x + threadIdx.x;
    if (i >= n4) return;
    float4 v = *(const float4*)&in[i * 4];
    uint2 u = make_uint2(packbf(v.x, v.y), packbf(v.z, v.w));
    *(uint2*)&out[i * 4] = u;
}

// transpose-convert: Wt[c][r] = W[r][c];  W: [R, Ncols]
__global__ void k_tcvt(const float* __restrict__ W, __nv_bfloat16* __restrict__ Wt,
                       int R, int Ncols) {
    int idx = blockIdx.x * blockDim.x + threadIdx.x;
    if (idx >= R * Ncols) return;
    int r = idx / Ncols, c = idx % Ncols;
    Wt[(long)c * R + r] = __float2bfloat16(W[idx]);
}

// ---------------- folds (exact fp32) -----------------------------------------------
__global__ void k_fold_attn(const float* __restrict__ W, const float* __restrict__ asrc,
                            const float* __restrict__ adst, float* __restrict__ V, int K) {
    int idx = blockIdx.x * blockDim.x + threadIdx.x;
    if (idx >= K * 16) return;
    int k = idx >> 4;
    int col = idx & 15;
    int h = col & 7;
    const float* att = (col & 8) ? adst : asrc;
    float acc = 0.f;
#pragma unroll 8
    for (int f = 0; f < F2C; f++)
        acc += W[(long)k * D1 + h * F2C + f] * att[h * F2C + f];
    V[idx] = acc;
}

// ---------------- attention logits from input features ------------------------------
template <int K>
__global__ __launch_bounds__(256) void k_attnx(const float* __restrict__ feat,
                                               const float* __restrict__ V) {
    __shared__ float sV[K * 17];
    int tid = threadIdx.x;
    for (int idx = tid; idx < K * 16; idx += 256) {
        int k = idx >> 4, c = idx & 15;
        sV[k * 17 + c] = V[idx];
    }
    __syncthreads();
    int warp = tid >> 5, lane = tid & 31;
    int n = blockIdx.x * 8 + warp;
    if (n >= NN) return;
    float xv[K / 32];
#pragma unroll
    for (int c = 0; c < K / 32; c++) xv[c] = feat[(long)n * K + c * 32 + lane];
    float acc[16];
#pragma unroll
    for (int h = 0; h < 16; h++) acc[h] = 0.f;
#pragma unroll
    for (int c = 0; c < K / 32; c++) {
        int k = c * 32 + lane;
#pragma unroll
        for (int h = 0; h < 16; h++) acc[h] += xv[c] * sV[k * 17 + h];
    }
#pragma unroll
    for (int off = 16; off > 0; off >>= 1)
#pragma unroll
        for (int h = 0; h < 16; h++)
            acc[h] += __shfl_xor_sync(0xffffffffu, acc[h], off);
    if (lane == 0) {
#pragma unroll
        for (int h = 0; h < 8; h++) {
            g_as[n * HC + h] = acc[h];
            g_ad[n * HC + h] = acc[8 + h];
        }
    }
}

// ---------------- per (node,head) online softmax stats --------------------------------
__global__ void k_stats() {
    int idx = blockIdx.x * blockDim.x + threadIdx.x;
    if (idx >= NN * HC) return;
    int n = idx >> 3, h = idx & 7;
    float adn = g_ad[idx];
    int beg = g_offs[n], end = g_offs[n + 1];
    int src = g_csrc[beg];
    float e = lrelu(g_as[src * HC + h] + adn);
    float mx = e, s = 1.0f;
    for (int j = beg + 1; j < end; j++) {
        src = g_csrc[j];
        e = lrelu(g_as[src * HC + h] + adn);
        if (e > mx) { s *= __expf(mx - e); mx = e; }
        s += __expf(e - mx);
    }
    g_m[idx] = mx;
    g_den[idx] = s;
}

// ---------------- aggregation from bf16 source; templated output ----------------------
template <typename TO>
__device__ __forceinline__ void storeAgg(TO* out, long base, float4 a);
template <>
__device__ __forceinline__ void storeAgg<float>(float* out, long base, float4 a) {
    *(float4*)&out[base] = a;
}
template <>
__device__ __forceinline__ void storeAgg<__nv_bfloat16>(__nv_bfloat16* out, long base, float4 a) {
    uint2 u = make_uint2(packbf(a.x, a.y), packbf(a.z, a.w));
    *(uint2*)&out[base] = u;
}

template <typename TO>
__global__ __launch_bounds__(128) void k_agg(const __nv_bfloat16* __restrict__ hsrc,
                                             const float* __restrict__ bias,
                                             TO* __restrict__ out) {
    int n = blockIdx.x;
    int t = threadIdx.x;
    int h = t >> 4;
    float adn = g_ad[n * HC + h];
    float mn  = g_m[n * HC + h];
    float inv = 1.0f / (g_den[n * HC + h] + 1e-16f);
    int beg = g_offs[n], end = g_offs[n + 1];
    float4 acc = make_float4(0.f, 0.f, 0.f, 0.f);
    int j = beg;
    for (; j + 1 < end; j += 2) {
        int s0 = g_csrc[j];
        int s1 = g_csrc[j + 1];
        float e0 = lrelu(g_as[s0 * HC + h] + adn);
        float e1 = lrelu(g_as[s1 * HC + h] + adn);
        float a0 = __expf(e0 - mn) * inv;
        float a1 = __expf(e1 - mn) * inv;
        uint2 u0 = *(const uint2*)&hsrc[(long)s0 * D1 + t * 4];
        uint2 u1 = *(const uint2*)&hsrc[(long)s1 * D1 + t * 4];
        float2 p0 = __bfloat1622float2(*(__nv_bfloat162*)&u0.x);
        float2 p1 = __bfloat1622float2(*(__nv_bfloat162*)&u0.y);
        float2 q0 = __bfloat1622float2(*(__nv_bfloat162*)&u1.x);
        float2 q1 = __bfloat1622float2(*(__nv_bfloat162*)&u1.y);
        acc.x += a0 * p0.x + a1 * q0.x;
        acc.y += a0 * p0.y + a1 * q0.y;
        acc.z += a0 * p1.x + a1 * q1.x;
        acc.w += a0 * p1.y + a1 * q1.y;
    }
    if (j < end) {
        int s = g_csrc[j];
        float e = lrelu(g_as[s * HC + h] + adn);
        float a0 = __expf(e - mn) * inv;
        uint2 u0 = *(const uint2*)&hsrc[(long)s * D1 + t * 4];
        float2 p0 = __bfloat1622float2(*(__nv_bfloat162*)&u0.x);
        float2 p1 = __bfloat1622float2(*(__nv_bfloat162*)&u0.y);
        acc.x += a0 * p0.x;
        acc.y += a0 * p0.y;
        acc.z += a0 * p1.x;
        acc.w += a0 * p1.y;
    }
    float4 b = *(const float4*)&bias[t * 4];
    acc.x += b.x; acc.y += b.y; acc.z += b.z; acc.w += b.w;
    storeAgg<TO>(out, (long)n * D1 + t * 4, acc);
}

// ---------------- bf16 TN GEMM: C[M,N] = A[M,K] @ Bt[N,K]^T -------------------------
// 128x128 tile, BK=32, m16n8k16, 8 warps (4x2), warp tile 32x64.
template <typename TO>
__device__ __forceinline__ void storeC2(TO* C, long idx, float a, float b);
template <>
__device__ __forceinline__ void storeC2<float>(float* C, long idx, float a, float b) {
    *(float2*)&C[idx] = make_float2(a, b);
}
template <>
__device__ __forceinline__ void storeC2<__nv_bfloat16>(__nv_bfloat16* C, long idx, float a, float b) {
    unsigned u = packbf(a, b);
    *(unsigned*)&C[idx] = u;
}

template <typename TO>
__global__ __launch_bounds__(256) void k_bgemm(int M, int N, int K,
                                               const __nv_bfloat16* __restrict__ A,
                                               const __nv_bfloat16* __restrict__ Bt,
                                               TO* __restrict__ C) {
    // [row][kpair] as uint (bf16x2), stride 20 -> conflict-free fragment loads
    __shared__ unsigned As[128][20];
    __shared__ unsigned Bs[128][20];
    int tid  = threadIdx.x;
    int lane = tid & 31;
    int warp = tid >> 5;
    int wr = warp & 3;
    int wc = warp >> 2;
    int blockRow = blockIdx.y * 128;
    int blockCol = blockIdx.x * 128;

    float acc[2][8][4];
#pragma unroll
    for (int i = 0; i < 2; i++)
#pragma unroll
        for (int j = 0; j < 8; j++)
#pragma unroll
            for (int q = 0; q < 4; q++) acc[i][j][q] = 0.0f;

    // staging: 2 uint4 tasks per thread per operand; idx = tid + i*256
    // r = idx>>2 (0..127), c = idx&3 (uint4 covering kpairs 4c..4c+3 = bf16 cols 8c..8c+7)
    uint4 pa[2], pb[2];
#pragma unroll
    for (int i = 0; i < 2; i++) {
        int idx = tid + i * 256;
        int r = idx >> 2, c = idx & 3;
        pa[i] = make_uint4(0, 0, 0, 0);
        if (blockRow + r < M)
            pa[i] = *(const uint4*)&A[(long)(blockRow + r) * K + c * 8];
        pb[i] = *(const uint4*)&Bt[(long)(blockCol + r) * K + c * 8];
    }

    for (int k0 = 0; k0 < K; k0 += 32) {
#pragma unroll
        for (int i = 0; i < 2; i++) {
            int idx = tid + i * 256;
            int r = idx >> 2, c = idx & 3;
            *(uint4*)&As[r][c * 4] = pa[i];
            *(uint4*)&Bs[r][c * 4] = pb[i];
        }
        __syncthreads();

        if (k0 + 32 < K) {
#pragma unroll
            for (int i = 0; i < 2; i++) {
                int idx = tid + i * 256;
                int r = idx >> 2, c = idx & 3;
                pa[i] = make_uint4(0, 0, 0, 0);
                if (blockRow + r < M)
                    pa[i] = *(const uint4*)&A[(long)(blockRow + r) * K + k0 + 32 + c * 8];
                pb[i] = *(const uint4*)&Bt[(long)(blockCol + r) * K + k0 + 32 + c * 8];
            }
        }

#pragma unroll
        for (int ks = 0; ks < 2; ks++) {
            int kb = ks * 8 + (lane & 3);
            unsigned a[2][4], b[8][2];
            int r0 = wr * 32 + (lane >> 2);
#pragma unroll
            for (int i = 0; i < 2; i++) {
                a[i][0] = As[r0 + i * 16][kb];
                a[i][1] = As[r0 + i * 16 + 8][kb];
                a[i][2] = As[r0 + i * 16][kb + 4];
                a[i][3] = As[r0 + i * 16 + 8][kb + 4];
            }
            int bn = wc * 64 + (lane >> 2);
#pragma unroll
            for (int j = 0; j < 8; j++) {
                b[j][0] = Bs[bn + j * 8][kb];
                b[j][1] = Bs[bn + j * 8][kb + 4];
            }
#pragma unroll
            for (int i = 0; i < 2; i++) {
#pragma unroll
                for (int j = 0; j < 8; j++) {
                    asm volatile(
                        "mma.sync.aligned.m16n8k16.row.col.f32.bf16.bf16.f32 "
                        "{%0,%1,%2,%3}, {%4,%5,%6,%7}, {%8,%9}, {%0,%1,%2,%3};"
                        : "+f"(acc[i][j][0]), "+f"(acc[i][j][1]),
                          "+f"(acc[i][j][2]), "+f"(acc[i][j][3])
                        : "r"(a[i][0]), "r"(a[i][1]), "r"(a[i][2]), "r"(a[i][3]),
                          "r"(b[j][0]), "r"(b[j][1]));
                }
            }
        }
        __syncthreads();
    }

#pragma unroll
    for (int i = 0; i < 2; i++) {
        int r = blockRow + wr * 32 + i * 16 + (lane >> 2);
#pragma unroll
        for (int j = 0; j < 8; j++) {
            int c = blockCol + wc * 64 + j * 8 + (lane & 3) * 2;
            if (r < M)
                storeC2<TO>(C, (long)r * N + c, acc[i][j][0], acc[i][j][1]);
            if (r + 8 < M)
                storeC2<TO>(C, (long)(r + 8) * N + c, acc[i][j][2], acc[i][j][3]);
        }
    }
}

// ---------------- LSTM elementwise + relu; dual-format output --------------------------
__global__ void k_lstm(const float* __restrict__ b_ih, const float* __restrict__ b_hh) {
    int idx = blockIdx.x * blockDim.x + threadIdx.x;
    if (idx >= NN * F2C) return;
    int n = idx >> 6, j = idx & 63;
    const float* g = g_gates + (long)n * G4;
    float i_ = g[j]       + b_ih[j]       + b_hh[j];
    float gg = g[128 + j] + b_ih[128 + j] + b_hh[128 + j];
    float o_ = g[192 + j] + b_ih[192 + j] + b_hh[192 + j];
    float c  = sigf(i_) * tanhf(gg);
    float hh = sigf(o_) * tanhf(c);
    float r  = fmaxf(hh, 0.0f);
    g_h2[idx]  = r;
    g_h2b[idx] = __float2bfloat16(r);
}

// ---------------- row softmax over 512 --------------------------------------------------
__global__ __launch_bounds__(256) void k_softmax(const float* __restrict__ in,
                                                 float* __restrict__ out) {
    __shared__ float red[256];
    int n = blockIdx.x, t = threadIdx.x;
    float a = in[(long)n * D1 + t];
    float b = in[(long)n * D1 + 256 + t];
    red[t] = fmaxf(a, b);
    __syncthreads();
#pragma unroll
    for (int o = 128; o > 0; o >>= 1) {
        if (t < o) red[t] = fmaxf(red[t], red[t + o]);
        __syncthreads();
    }
    float mx = red[0];
    __syncthreads();
    float ea = __expf(a - mx), eb = __expf(b - mx);
    red[t] = ea + eb;
    __syncthreads();
#pragma unroll
    for (int o = 128; o > 0; o >>= 1) {
        if (t < o) red[t] += red[t + o];
        __syncthreads();
    }
    float inv = 1.0f / red[0];
    out[(long)n * D1 + t] = ea * inv;
    out[(long)n * D1 + 256 + t] = eb * inv;
}

// ---------------- launch ------------------------------------------------------------------
extern "C" void kernel_launch(void* const* d_in, const int* in_sizes, int n_in,
                              void* d_out, int out_size) {
    const float* x        = (const float*)d_in[0];
    const int*   ei       = (const int*)d_in[1];
    const float* W1       = (const float*)d_in[3];
    const float* att_src1 = (const float*)d_in[4];
    const float* att_dst1 = (const float*)d_in[5];
    const float* bias1    = (const float*)d_in[6];
    const float* W_ih     = (const float*)d_in[7];
    const float* b_ih     = (const float*)d_in[9];
    const float* b_hh     = (const float*)d_in[10];
    const float* W2       = (const float*)d_in[11];
    const float* att_src2 = (const float*)d_in[12];
    const float* att_dst2 = (const float*)d_in[13];
    const float* bias2    = (const float*)d_in[14];
    float* out = (float*)d_out;

    int E = in_sizes[1] / 2;
    int etot = E + NN;

    void* p_deg = nullptr;   cudaGetSymbolAddress(&p_deg, g_deg);
    void* p_v1 = nullptr;    cudaGetSymbolAddress(&p_v1, g_v1);
    void* p_v2 = nullptr;    cudaGetSymbolAddress(&p_v2, g_v2);
    void* p_xb = nullptr;    cudaGetSymbolAddress(&p_xb, g_xb);
    void* p_W1b = nullptr;   cudaGetSymbolAddress(&p_W1b, g_W1b);
    void* p_Wihb = nullptr;  cudaGetSymbolAddress(&p_Wihb, g_Wihb);
    void* p_W2b = nullptr;   cudaGetSymbolAddress(&p_W2b, g_W2b);
    void* p_h1b = nullptr;   cudaGetSymbolAddress(&p_h1b, g_h1b);
    void* p_agg1b = nullptr; cudaGetSymbolAddress(&p_agg1b, g_agg1b);
    void* p_gates = nullptr; cudaGetSymbolAddress(&p_gates, g_gates);
    void* p_h2 = nullptr;    cudaGetSymbolAddress(&p_h2, g_h2);
    void* p_h2b = nullptr;   cudaGetSymbolAddress(&p_h2b, g_h2b);
    void* p_h3b = nullptr;   cudaGetSymbolAddress(&p_h3b, g_h3b);
    void* p_pre = nullptr;   cudaGetSymbolAddress(&p_pre, g_pre);

    cudaMemsetAsync(p_deg, 0, NN * sizeof(int), 0);
    k_cvt<<<(NN * FIN / 4 + 255) / 256, 256>>>(x, (__nv_bfloat16*)p_xb, NN * FIN / 4);
    k_tcvt<<<(FIN * D1 + 255) / 256, 256>>>(W1, (__nv_bfloat16*)p_W1b, FIN, D1);
    k_degree<<<(etot + 255) / 256, 256>>>(ei, E);

    // GEMM1: h1b = xb @ W1b^T   [20000,128]x[512,128]^T
    {
        dim3 grid(D1 / 128, (NN + 127) / 128);
        k_bgemm<__nv_bfloat16><<<grid, 256>>>(NN, D1, FIN, (const __nv_bfloat16*)p_xb,
                                              (const __nv_bfloat16*)p_W1b,
                                              (__nv_bfloat16*)p_h1b);
    }

    k_scan<<<1, 1024>>>();
    k_scatter<<<(etot + 255) / 256, 256>>>(ei, E);
    k_cvt<<<(G4 * D1 / 4 + 255) / 256, 256>>>(W_ih, (__nv_bfloat16*)p_Wihb, G4 * D1 / 4);
    k_tcvt<<<(F2C * D1 + 255) / 256, 256>>>(W2, (__nv_bfloat16*)p_W2b, F2C, D1);
    k_fold_attn<<<(FIN * 16 + 255) / 256, 256>>>(W1, att_src1, att_dst1, (float*)p_v1, FIN);
    k_fold_attn<<<(F2C * 16 + 255) / 256, 256>>>(W2, att_src2, att_dst2, (float*)p_v2, F2C);

    // ---- layer 1 ----
    k_attnx<FIN><<<2500, 256>>>(x, (const float*)p_v1);
    k_stats<<<(NN * HC + 255) / 256, 256>>>();
    k_agg<__nv_bfloat16><<<NN, 128>>>((const __nv_bfloat16*)p_h1b, bias1,
                                      (__nv_bfloat16*)p_agg1b);
    // GEMM2: gates = agg1b @ W_ih^T   [20000,512]x[256,512]^T
    {
        dim3 grid(G4 / 128, (NN + 127) / 128);
        k_bgemm<float><<<grid, 256>>>(NN, G4, D1, (const __nv_bfloat16*)p_agg1b,
                                      (const __nv_bfloat16*)p_Wihb, (float*)p_gates);
    }
    k_lstm<<<(NN * F2C + 255) / 256, 256>>>(b_ih, b_hh);

    // ---- layer 2 ----
    // GEMM3: h3b = h2b @ W2b^T   [20000,64]x[512,64]^T
    {
        dim3 grid(D1 / 128, (NN + 127) / 128);
        k_bgemm<__nv_bfloat16><<<grid, 256>>>(NN, D1, F2C, (const __nv_bfloat16*)p_h2b,
                                              (const __nv_bfloat16*)p_W2b,
                                              (__nv_bfloat16*)p_h3b);
    }
    k_attnx<F2C><<<2500, 256>>>((const float*)p_h2, (const float*)p_v2);
    k_stats<<<(NN * HC + 255) / 256, 256>>>();
    k_agg<float><<<NN, 128>>>((const __nv_bfloat16*)p_h3b, bias2, (float*)p_pre);
    k_softmax<<<NN, 256>>>((const float*)p_pre, out);
}

// round 8
// speedup vs baseline: 1.6504x; 1.0134x over previous
#include <cuda_runtime.h>
#include <cuda_bf16.h>
#include <math.h>

#define NN 20000
#define EE 320000
#define ET (EE + NN)
#define FIN 128
#define F2C 64
#define HC 8
#define D1 512
#define G4 256

// ---------------- scratch ----------------------------------------------------
__device__ float g_v1[FIN * 16];
__device__ float g_v2[F2C * 16];
__device__ __nv_bfloat16 g_xb[NN * FIN];     // x bf16
__device__ __nv_bfloat16 g_W1b[D1 * FIN];    // W1^T bf16 [512,128]
__device__ __nv_bfloat16 g_Wihb[G4 * D1];    // W_ih bf16 [256,512] (already B^T)
__device__ __nv_bfloat16 g_W2b[D1 * F2C];    // W2^T bf16 [512,64]
__device__ __nv_bfloat16 g_h1b[NN * D1];     // GEMM1 out (gather source)
__device__ __nv_bfloat16 g_agg1b[NN * D1];   // GAT1 out (bf16, feeds GEMM2)
__device__ float g_gates[NN * G4];
__device__ float g_h2[NN * F2C];             // fp32 (attn logits)
__device__ __nv_bfloat16 g_h2b[NN * F2C];    // bf16 (GEMM3 A)
__device__ __nv_bfloat16 g_h3b[NN * D1];     // GEMM3 out (gather source)
__device__ float g_pre[NN * D1];             // pre-softmax fp32
__device__ float g_as[NN * HC];
__device__ float g_ad[NN * HC];
__device__ float g_m[NN * HC];
__device__ float g_den[NN * HC];
__device__ int   g_deg[NN];
__device__ int   g_offs[NN + 1];
__device__ int   g_cur[NN];
__device__ int   g_csrc[ET];

__device__ __forceinline__ float sigf(float x) { return 1.0f / (1.0f + __expf(-x)); }
__device__ __forceinline__ float lrelu(float e) { return (e > 0.f) ? e : 0.2f * e; }
__device__ __forceinline__ unsigned packbf(float a, float b) {
    __nv_bfloat162 t = __floats2bfloat162_rn(a, b);
    return *(unsigned*)&t;
}

// ---------------- CSR build ----------------------------------------------------
__global__ void k_degree(const int* __restrict__ ei, int E) {
    int i = blockIdx.x * blockDim.x + threadIdx.x;
    if (i >= E + NN) return;
    int dst = (i < E) ? ei[E + i] : (i - E);
    atomicAdd(&g_deg[dst], 1);
}

__global__ void k_scan() {
    __shared__ int sums[1024];
    const int CH = 20;
    int t = threadIdx.x;
    int b = t * CH;
    int e = min(b + CH, NN);
    int tmp[CH];
    int local = 0;
    for (int i = b; i < e; i++) { tmp[i - b] = g_deg[i]; local += tmp[i - b]; }
    sums[t] = local;
    __syncthreads();
    for (int o = 1; o < 1024; o <<= 1) {
        int v = (t >= o) ? sums[t - o] : 0;
        __syncthreads();
        sums[t] += v;
        __syncthreads();
    }
    int run = sums[t] - local;
    for (int i = b; i < e; i++) {
        g_offs[i] = run;
        g_cur[i]  = run;
        run += tmp[i - b];
    }
    if (b < NN && e == NN) g_offs[NN] = run;
}

__global__ void k_scatter(const int* __restrict__ ei, int E) {
    int i = blockIdx.x * blockDim.x + threadIdx.x;
    if (i >= E + NN) return;
    int src, dst;
    if (i < E) { src = ei[i]; dst = ei[E + i]; }
    else       { src = dst = i - E; }
    int pos = atomicAdd(&g_cur[dst], 1);
    g_csrc[pos] = src;
}

// ---------------- conversions ----------------------------------------------------
__global__ void k_cvt(const float* __restrict__ in, __nv_bfloat16* __restrict__ out, int n4) {
    int i = blockIdx.x * blockDim.x + threadIdx.x;
    if (i >= n4) return;
    float4 v = *(const float4*)&in[i * 4];
    uint2 u = make_uint2(packbf(v.x, v.y), packbf(v.z, v.w));
    *(uint2*)&out[i * 4] = u;
}

__global__ void k_tcvt(const float* __restrict__ W, __nv_bfloat16* __restrict__ Wt,
                       int R, int Ncols) {
    int idx = blockIdx.x * blockDim.x + threadIdx.x;
    if (idx >= R * Ncols) return;
    int r = idx / Ncols, c = idx % Ncols;
    Wt[(long)c * R + r] = __float2bfloat16(W[idx]);
}

// ---------------- folds (exact fp32) -----------------------------------------------
__global__ void k_fold_attn(const float* __restrict__ W, const float* __restrict__ asrc,
                            const float* __restrict__ adst, float* __restrict__ V, int K) {
    int idx = blockIdx.x * blockDim.x + threadIdx.x;
    if (idx >= K * 16) return;
    int k = idx >> 4;
    int col = idx & 15;
    int h = col & 7;
    const float* att = (col & 8) ? adst : asrc;
    float acc = 0.f;
#pragma unroll 8
    for (int f = 0; f < F2C; f++)
        acc += W[(long)k * D1 + h * F2C + f] * att[h * F2C + f];
    V[idx] = acc;
}

// ---------------- attention logits from input features ------------------------------
template <int K>
__global__ __launch_bounds__(256) void k_attnx(const float* __restrict__ feat,
                                               const float* __restrict__ V) {
    __shared__ float sV[K * 17];
    int tid = threadIdx.x;
    for (int idx = tid; idx < K * 16; idx += 256) {
        int k = idx >> 4, c = idx & 15;
        sV[k * 17 + c] = V[idx];
    }
    __syncthreads();
    int warp = tid >> 5, lane = tid & 31;
    int n = blockIdx.x * 8 + warp;
    if (n >= NN) return;
    float xv[K / 32];
#pragma unroll
    for (int c = 0; c < K / 32; c++) xv[c] = feat[(long)n * K + c * 32 + lane];
    float acc[16];
#pragma unroll
    for (int h = 0; h < 16; h++) acc[h] = 0.f;
#pragma unroll
    for (int c = 0; c < K / 32; c++) {
        int k = c * 32 + lane;
#pragma unroll
        for (int h = 0; h < 16; h++) acc[h] += xv[c] * sV[k * 17 + h];
    }
#pragma unroll
    for (int off = 16; off > 0; off >>= 1)
#pragma unroll
        for (int h = 0; h < 16; h++)
            acc[h] += __shfl_xor_sync(0xffffffffu, acc[h], off);
    if (lane == 0) {
#pragma unroll
        for (int h = 0; h < 8; h++) {
            g_as[n * HC + h] = acc[h];
            g_ad[n * HC + h] = acc[8 + h];
        }
    }
}

// ---------------- per (node,head) online softmax stats --------------------------------
__global__ void k_stats() {
    int idx = blockIdx.x * blockDim.x + threadIdx.x;
    if (idx >= NN * HC) return;
    int n = idx >> 3, h = idx & 7;
    float adn = g_ad[idx];
    int beg = g_offs[n], end = g_offs[n + 1];
    int src = g_csrc[beg];
    float e = lrelu(g_as[src * HC + h] + adn);
    float mx = e, s = 1.0f;
    for (int j = beg + 1; j < end; j++) {
        src = g_csrc[j];
        e = lrelu(g_as[src * HC + h] + adn);
        if (e > mx) { s *= __expf(mx - e); mx = e; }
        s += __expf(e - mx);
    }
    g_m[idx] = mx;
    g_den[idx] = s;
}

// ---------------- aggregation from bf16 source; templated output ----------------------
template <typename TO>
__device__ __forceinline__ void storeAgg(TO* out, long base, float4 a);
template <>
__device__ __forceinline__ void storeAgg<float>(float* out, long base, float4 a) {
    *(float4*)&out[base] = a;
}
template <>
__device__ __forceinline__ void storeAgg<__nv_bfloat16>(__nv_bfloat16* out, long base, float4 a) {
    uint2 u = make_uint2(packbf(a.x, a.y), packbf(a.z, a.w));
    *(uint2*)&out[base] = u;
}

template <typename TO>
__global__ __launch_bounds__(128) void k_agg(const __nv_bfloat16* __restrict__ hsrc,
                                             const float* __restrict__ bias,
                                             TO* __restrict__ out) {
    int n = blockIdx.x;
    int t = threadIdx.x;
    int h = t >> 4;
    float adn = g_ad[n * HC + h];
    float mn  = g_m[n * HC + h];
    float inv = 1.0f / (g_den[n * HC + h] + 1e-16f);
    int beg = g_offs[n], end = g_offs[n + 1];
    float4 acc = make_float4(0.f, 0.f, 0.f, 0.f);
    int j = beg;
    for (; j + 1 < end; j += 2) {
        int s0 = g_csrc[j];
        int s1 = g_csrc[j + 1];
        float e0 = lrelu(g_as[s0 * HC + h] + adn);
        float e1 = lrelu(g_as[s1 * HC + h] + adn);
        float a0 = __expf(e0 - mn) * inv;
        float a1 = __expf(e1 - mn) * inv;
        uint2 u0 = *(const uint2*)&hsrc[(long)s0 * D1 + t * 4];
        uint2 u1 = *(const uint2*)&hsrc[(long)s1 * D1 + t * 4];
        float2 p0 = __bfloat1622float2(*(__nv_bfloat162*)&u0.x);
        float2 p1 = __bfloat1622float2(*(__nv_bfloat162*)&u0.y);
        float2 q0 = __bfloat1622float2(*(__nv_bfloat162*)&u1.x);
        float2 q1 = __bfloat1622float2(*(__nv_bfloat162*)&u1.y);
        acc.x += a0 * p0.x + a1 * q0.x;
        acc.y += a0 * p0.y + a1 * q0.y;
        acc.z += a0 * p1.x + a1 * q1.x;
        acc.w += a0 * p1.y + a1 * q1.y;
    }
    if (j < end) {
        int s = g_csrc[j];
        float e = lrelu(g_as[s * HC + h] + adn);
        float a0 = __expf(e - mn) * inv;
        uint2 u0 = *(const uint2*)&hsrc[(long)s * D1 + t * 4];
        float2 p0 = __bfloat1622float2(*(__nv_bfloat162*)&u0.x);
        float2 p1 = __bfloat1622float2(*(__nv_bfloat162*)&u0.y);
        acc.x += a0 * p0.x;
        acc.y += a0 * p0.y;
        acc.z += a0 * p1.x;
        acc.w += a0 * p1.y;
    }
    float4 b = *(const float4*)&bias[t * 4];
    acc.x += b.x; acc.y += b.y; acc.z += b.z; acc.w += b.w;
    storeAgg<TO>(out, (long)n * D1 + t * 4, acc);
}

// ---------------- bf16 TN GEMM with ldmatrix fragments -------------------------------
// C[M,N] = A[M,K] @ Bt[N,K]^T. 128x128 tile, BK=32, m16n8k16, 8 warps (4x2).
// SMEM row stride 36 uints (144B): ldmatrix 8-row phases are conflict-free (4r mod 32).
#define SROW 36

template <typename TO>
__device__ __forceinline__ void storeC2(TO* C, long idx, float a, float b);
template <>
__device__ __forceinline__ void storeC2<float>(float* C, long idx, float a, float b) {
    *(float2*)&C[idx] = make_float2(a, b);
}
template <>
__device__ __forceinline__ void storeC2<__nv_bfloat16>(__nv_bfloat16* C, long idx, float a, float b) {
    unsigned u = packbf(a, b);
    *(unsigned*)&C[idx] = u;
}

__device__ __forceinline__ void ldsm4(unsigned& r0, unsigned& r1, unsigned& r2, unsigned& r3,
                                      unsigned addr) {
    asm volatile("ldmatrix.sync.aligned.m8n8.x4.shared.b16 {%0,%1,%2,%3}, [%4];"
                 : "=r"(r0), "=r"(r1), "=r"(r2), "=r"(r3) : "r"(addr));
}

template <typename TO>
__global__ __launch_bounds__(256) void k_bgemm(int M, int N, int K,
                                               const __nv_bfloat16* __restrict__ A,
                                               const __nv_bfloat16* __restrict__ Bt,
                                               TO* __restrict__ C) {
    __shared__ unsigned As[128][SROW];
    __shared__ unsigned Bs[128][SROW];
    int tid  = threadIdx.x;
    int lane = tid & 31;
    int warp = tid >> 5;
    int wr = warp & 3;
    int wc = warp >> 2;
    int blockRow = blockIdx.y * 128;
    int blockCol = blockIdx.x * 128;

    float acc[2][8][4];
#pragma unroll
    for (int i = 0; i < 2; i++)
#pragma unroll
        for (int j = 0; j < 8; j++)
#pragma unroll
            for (int q = 0; q < 4; q++) acc[i][j][q] = 0.0f;

    // per-lane ldmatrix byte offsets (within SMEM tile, before k-step offset)
    unsigned asBase = (unsigned)__cvta_generic_to_shared(&As[0][0]);
    unsigned bsBase = (unsigned)__cvta_generic_to_shared(&Bs[0][0]);
    int sub = lane >> 3;        // matrix id 0..3
    int l7  = lane & 7;
    unsigned aAddr[2];
#pragma unroll
    for (int i = 0; i < 2; i++) {
        int row = wr * 32 + i * 16 + (sub & 1) * 8 + l7;   // m0:r0-7 m1:r8-15 (kb0), m2/m3 at +16B
        aAddr[i] = asBase + row * (SROW * 4) + (sub >> 1) * 16;
    }
    unsigned bAddr[4];
#pragma unroll
    for (int jj = 0; jj < 4; jj++) {                        // tile pair (2jj, 2jj+1)
        int tile = jj * 2 + (sub >> 1);
        int row = wc * 64 + tile * 8 + l7;
        bAddr[jj] = bsBase + row * (SROW * 4) + (sub & 1) * 16;
    }

    // staging: idx = tid + i*256; r = idx>>2 (0..127), c = idx&3 (uint4 = 8 bf16 cols)
    uint4 pa[2], pb[2];
#pragma unroll
    for (int i = 0; i < 2; i++) {
        int idx = tid + i * 256;
        int r = idx >> 2, c = idx & 3;
        pa[i] = make_uint4(0, 0, 0, 0);
        if (blockRow + r < M)
            pa[i] = *(const uint4*)&A[(long)(blockRow + r) * K + c * 8];
        pb[i] = *(const uint4*)&Bt[(long)(blockCol + r) * K + c * 8];
    }

    for (int k0 = 0; k0 < K; k0 += 32) {
#pragma unroll
        for (int i = 0; i < 2; i++) {
            int idx = tid + i * 256;
            int r = idx >> 2, c = idx & 3;
            *(uint4*)&As[r][c * 4] = pa[i];
            *(uint4*)&Bs[r][c * 4] = pb[i];
        }
        __syncthreads();

        if (k0 + 32 < K) {
#pragma unroll
            for (int i = 0; i < 2; i++) {
                int idx = tid + i * 256;
                int r = idx >> 2, c = idx & 3;
                pa[i] = make_uint4(0, 0, 0, 0);
                if (blockRow + r < M)
                    pa[i] = *(const uint4*)&A[(long)(blockRow + r) * K + k0 + 32 + c * 8];
                pb[i] = *(const uint4*)&Bt[(long)(blockCol + r) * K + k0 + 32 + c * 8];
            }
        }

#pragma unroll
        for (int ks = 0; ks < 2; ks++) {
            unsigned kadd = ks * 32;                       // 16 bf16 = 32B per k-step
            unsigned a[2][4], b[8][2];
#pragma unroll
            for (int i = 0; i < 2; i++)
                ldsm4(a[i][0], a[i][1], a[i][2], a[i][3], aAddr[i] + kadd);
#pragma unroll
            for (int jj = 0; jj < 4; jj++)
                ldsm4(b[jj * 2][0], b[jj * 2][1], b[jj * 2 + 1][0], b[jj * 2 + 1][1],
                      bAddr[jj] + kadd);
#pragma unroll
            for (int i = 0; i < 2; i++) {
#pragma unroll
                for (int j = 0; j < 8; j++) {
                    asm volatile(
                        "mma.sync.aligned.m16n8k16.row.col.f32.bf16.bf16.f32 "
                        "{%0,%1,%2,%3}, {%4,%5,%6,%7}, {%8,%9}, {%0,%1,%2,%3};"
                        : "+f"(acc[i][j][0]), "+f"(acc[i][j][1]),
                          "+f"(acc[i][j][2]), "+f"(acc[i][j][3])
                        : "r"(a[i][0]), "r"(a[i][1]), "r"(a[i][2]), "r"(a[i][3]),
                          "r"(b[j][0]), "r"(b[j][1]));
                }
            }
        }
        __syncthreads();
    }

#pragma unroll
    for (int i = 0; i < 2; i++) {
        int r = blockRow + wr * 32 + i * 16 + (lane >> 2);
#pragma unroll
        for (int j = 0; j < 8; j++) {
            int c = blockCol + wc * 64 + j * 8 + (lane & 3) * 2;
            if (r < M)
                storeC2<TO>(C, (long)r * N + c, acc[i][j][0], acc[i][j][1]);
            if (r + 8 < M)
                storeC2<TO>(C, (long)(r + 8) * N + c, acc[i][j][2], acc[i][j][3]);
        }
    }
}

// ---------------- LSTM elementwise + relu; dual-format output --------------------------
__global__ void k_lstm(const float* __restrict__ b_ih, const float* __restrict__ b_hh) {
    int idx = blockIdx.x * blockDim.x + threadIdx.x;
    if (idx >= NN * F2C) return;
    int n = idx >> 6, j = idx & 63;
    const float* g = g_gates + (long)n * G4;
    float i_ = g[j]       + b_ih[j]       + b_hh[j];
    float gg = g[128 + j] + b_ih[128 + j] + b_hh[128 + j];
    float o_ = g[192 + j] + b_ih[192 + j] + b_hh[192 + j];
    float c  = sigf(i_) * tanhf(gg);
    float hh = sigf(o_) * tanhf(c);
    float r  = fmaxf(hh, 0.0f);
    g_h2[idx]  = r;
    g_h2b[idx] = __float2bfloat16(r);
}

// ---------------- row softmax over 512 --------------------------------------------------
__global__ __launch_bounds__(256) void k_softmax(const float* __restrict__ in,
                                                 float* __restrict__ out) {
    __shared__ float red[256];
    int n = blockIdx.x, t = threadIdx.x;
    float a = in[(long)n * D1 + t];
    float b = in[(long)n * D1 + 256 + t];
    red[t] = fmaxf(a, b);
    __syncthreads();
#pragma unroll
    for (int o = 128; o > 0; o >>= 1) {
        if (t < o) red[t] = fmaxf(red[t], red[t + o]);
        __syncthreads();
    }
    float mx = red[0];
    __syncthreads();
    float ea = __expf(a - mx), eb = __expf(b - mx);
    red[t] = ea + eb;
    __syncthreads();
#pragma unroll
    for (int o = 128; o > 0; o >>= 1) {
        if (t < o) red[t] += red[t + o];
        __syncthreads();
    }
    float inv = 1.0f / red[0];
    out[(long)n * D1 + t] = ea * inv;
    out[(long)n * D1 + 256 + t] = eb * inv;
}

// ---------------- launch ------------------------------------------------------------------
extern "C" void kernel_launch(void* const* d_in, const int* in_sizes, int n_in,
                              void* d_out, int out_size) {
    const float* x        = (const float*)d_in[0];
    const int*   ei       = (const int*)d_in[1];
    const float* W1       = (const float*)d_in[3];
    const float* att_src1 = (const float*)d_in[4];
    const float* att_dst1 = (const float*)d_in[5];
    const float* bias1    = (const float*)d_in[6];
    const float* W_ih     = (const float*)d_in[7];
    const float* b_ih     = (const float*)d_in[9];
    const float* b_hh     = (const float*)d_in[10];
    const float* W2       = (const float*)d_in[11];
    const float* att_src2 = (const float*)d_in[12];
    const float* att_dst2 = (const float*)d_in[13];
    const float* bias2    = (const float*)d_in[14];
    float* out = (float*)d_out;

    int E = in_sizes[1] / 2;
    int etot = E + NN;

    void* p_deg = nullptr;   cudaGetSymbolAddress(&p_deg, g_deg);
    void* p_v1 = nullptr;    cudaGetSymbolAddress(&p_v1, g_v1);
    void* p_v2 = nullptr;    cudaGetSymbolAddress(&p_v2, g_v2);
    void* p_xb = nullptr;    cudaGetSymbolAddress(&p_xb, g_xb);
    void* p_W1b = nullptr;   cudaGetSymbolAddress(&p_W1b, g_W1b);
    void* p_Wihb = nullptr;  cudaGetSymbolAddress(&p_Wihb, g_Wihb);
    void* p_W2b = nullptr;   cudaGetSymbolAddress(&p_W2b, g_W2b);
    void* p_h1b = nullptr;   cudaGetSymbolAddress(&p_h1b, g_h1b);
    void* p_agg1b = nullptr; cudaGetSymbolAddress(&p_agg1b, g_agg1b);
    void* p_gates = nullptr; cudaGetSymbolAddress(&p_gates, g_gates);
    void* p_h2 = nullptr;    cudaGetSymbolAddress(&p_h2, g_h2);
    void* p_h2b = nullptr;   cudaGetSymbolAddress(&p_h2b, g_h2b);
    void* p_h3b = nullptr;   cudaGetSymbolAddress(&p_h3b, g_h3b);
    void* p_pre = nullptr;   cudaGetSymbolAddress(&p_pre, g_pre);

    cudaMemsetAsync(p_deg, 0, NN * sizeof(int), 0);
    k_cvt<<<(NN * FIN / 4 + 255) / 256, 256>>>(x, (__nv_bfloat16*)p_xb, NN * FIN / 4);
    k_tcvt<<<(FIN * D1 + 255) / 256, 256>>>(W1, (__nv_bfloat16*)p_W1b, FIN, D1);
    k_degree<<<(etot + 255) / 256, 256>>>(ei, E);

    // GEMM1 (launch #5, profiled): h1b = xb @ W1b^T
    {
        dim3 grid(D1 / 128, (NN + 127) / 128);
        k_bgemm<__nv_bfloat16><<<grid, 256>>>(NN, D1, FIN, (const __nv_bfloat16*)p_xb,
                                              (const __nv_bfloat16*)p_W1b,
                                              (__nv_bfloat16*)p_h1b);
    }

    k_scan<<<1, 1024>>>();
    k_scatter<<<(etot + 255) / 256, 256>>>(ei, E);
    k_cvt<<<(G4 * D1 / 4 + 255) / 256, 256>>>(W_ih, (__nv_bfloat16*)p_Wihb, G4 * D1 / 4);
    k_tcvt<<<(F2C * D1 + 255) / 256, 256>>>(W2, (__nv_bfloat16*)p_W2b, F2C, D1);
    k_fold_attn<<<(FIN * 16 + 255) / 256, 256>>>(W1, att_src1, att_dst1, (float*)p_v1, FIN);
    k_fold_attn<<<(F2C * 16 + 255) / 256, 256>>>(W2, att_src2, att_dst2, (float*)p_v2, F2C);

    // ---- layer 1 ----
    k_attnx<FIN><<<2500, 256>>>(x, (const float*)p_v1);
    k_stats<<<(NN * HC + 255) / 256, 256>>>();
    k_agg<__nv_bfloat16><<<NN, 128>>>((const __nv_bfloat16*)p_h1b, bias1,
                                      (__nv_bfloat16*)p_agg1b);
    // GEMM2: gates = agg1b @ W_ih^T
    {
        dim3 grid(G4 / 128, (NN + 127) / 128);
        k_bgemm<float><<<grid, 256>>>(NN, G4, D1, (const __nv_bfloat16*)p_agg1b,
                                      (const __nv_bfloat16*)p_Wihb, (float*)p_gates);
    }
    k_lstm<<<(NN * F2C + 255) / 256, 256>>>(b_ih, b_hh);

    // ---- layer 2 ----
    // GEMM3: h3b = h2b @ W2b^T
    {
        dim3 grid(D1 / 128, (NN + 127) / 128);
        k_bgemm<__nv_bfloat16><<<grid, 256>>>(NN, D1, F2C, (const __nv_bfloat16*)p_h2b,
                                              (const __nv_bfloat16*)p_W2b,
                                              (__nv_bfloat16*)p_h3b);
    }
    k_attnx<F2C><<<2500, 256>>>((const float*)p_h2, (const float*)p_v2);
    k_stats<<<(NN * HC + 255) / 256, 256>>>();
    k_agg<float><<<NN, 128>>>((const __nv_bfloat16*)p_h3b, bias2, (float*)p_pre);
    k_softmax<<<NN, 256>>>((const float*)p_pre, out);
}

// round 9
// speedup vs baseline: 2.0241x; 1.2265x over previous
#include <cuda_runtime.h>
#include <cuda_bf16.h>
#include <math.h>

#define NN 20000
#define EE 320000
#define ET (EE + NN)
#define FIN 128
#define F2C 64
#define HC 8
#define D1 512
#define G4 256

// ---------------- scratch ----------------------------------------------------
__device__ float g_v1[FIN * 16];
__device__ float g_v2[F2C * 16];
__device__ __nv_bfloat16 g_xb[NN * FIN];     // x bf16
__device__ __nv_bfloat16 g_W1b[D1 * FIN];    // W1^T bf16 [512,128]
__device__ __nv_bfloat16 g_Wihb[G4 * D1];    // W_ih bf16 [256,512]
__device__ __nv_bfloat16 g_W2b[D1 * F2C];    // W2^T bf16 [512,64]
__device__ __nv_bfloat16 g_h1b[NN * D1];     // GEMM1 out (gather source)
__device__ __nv_bfloat16 g_agg1b[NN * D1];   // GAT1 out (bf16, feeds GEMM2)
__device__ float g_gates[NN * G4];
__device__ float g_h2[NN * F2C];             // fp32 (attn logits)
__device__ __nv_bfloat16 g_h2b[NN * F2C];    // bf16 (GEMM3 A)
__device__ __nv_bfloat16 g_h3b[NN * D1];     // GEMM3 out (gather source)
__device__ float g_as[NN * HC];
__device__ float g_ad[NN * HC];
__device__ int   g_deg[NN];
__device__ int   g_offs[NN + 1];
__device__ int   g_cur[NN];
__device__ int   g_csrc[ET];

__device__ __forceinline__ float sigf(float x) { return 1.0f / (1.0f + __expf(-x)); }
__device__ __forceinline__ float lrelu(float e) { return (e > 0.f) ? e : 0.2f * e; }
__device__ __forceinline__ unsigned packbf(float a, float b) {
    __nv_bfloat162 t = __floats2bfloat162_rn(a, b);
    return *(unsigned*)&t;
}

// ---------------- CSR build ----------------------------------------------------
__global__ void k_degree(const int* __restrict__ ei, int E) {
    int i = blockIdx.x * blockDim.x + threadIdx.x;
    if (i >= E + NN) return;
    int dst = (i < E) ? ei[E + i] : (i - E);
    atomicAdd(&g_deg[dst], 1);
}

__global__ void k_scan() {
    __shared__ int sums[1024];
    const int CH = 20;
    int t = threadIdx.x;
    int b = t * CH;
    int e = min(b + CH, NN);
    int tmp[CH];
    int local = 0;
    for (int i = b; i < e; i++) { tmp[i - b] = g_deg[i]; local += tmp[i - b]; }
    sums[t] = local;
    __syncthreads();
    for (int o = 1; o < 1024; o <<= 1) {
        int v = (t >= o) ? sums[t - o] : 0;
        __syncthreads();
        sums[t] += v;
        __syncthreads();
    }
    int run = sums[t] - local;
    for (int i = b; i < e; i++) {
        g_offs[i] = run;
        g_cur[i]  = run;
        run += tmp[i - b];
    }
    if (b < NN && e == NN) g_offs[NN] = run;
}

__global__ void k_scatter(const int* __restrict__ ei, int E) {
    int i = blockIdx.x * blockDim.x + threadIdx.x;
    if (i >= E + NN) return;
    int src, dst;
    if (i < E) { src = ei[i]; dst = ei[E + i]; }
    else       { src = dst = i - E; }
    int pos = atomicAdd(&g_cur[dst], 1);
    g_csrc[pos] = src;
}

// ---------------- conversions ----------------------------------------------------
__global__ void k_cvt(const float* __restrict__ in, __nv_bfloat16* __restrict__ out, int n4) {
    int i = blockIdx.x * blockDim.x + threadIdx.x;
    if (i >= n4) return;
    float4 v = *(const float4*)&in[i * 4];
    uint2 u = make_uint2(packbf(v.x, v.y), packbf(v.z, v.w));
    *(uint2*)&out[i * 4] = u;
}

// merged weight prep: W1^T (seg0), W_ih straight (seg1), W2^T (seg2)
__global__ void k_prepw(const float* __restrict__ W1, const float* __restrict__ Wih,
                        const float* __restrict__ W2) {
    int idx = blockIdx.x * blockDim.x + threadIdx.x;
    const int S0 = FIN * D1;          // 65536
    const int S1 = G4 * D1;           // 131072
    const int S2 = F2C * D1;          // 32768
    if (idx < S0) {
        int r = idx / D1, c = idx % D1;
        g_W1b[(long)c * FIN + r] = __float2bfloat16(W1[idx]);
    } else if (idx < S0 + S1) {
        int i = idx - S0;
        g_Wihb[i] = __float2bfloat16(Wih[i]);
    } else if (idx < S0 + S1 + S2) {
        int i = idx - S0 - S1;
        int r = i / D1, c = i % D1;
        g_W2b[(long)c * F2C + r] = __float2bfloat16(W2[i]);
    }
}

// merged fold_attn for both layers
__global__ void k_folds(const float* __restrict__ W1, const float* __restrict__ as1,
                        const float* __restrict__ ad1,
                        const float* __restrict__ W2, const float* __restrict__ as2,
                        const float* __restrict__ ad2) {
    int idx = blockIdx.x * blockDim.x + threadIdx.x;
    const int N1 = FIN * 16;
    const int N2 = F2C * 16;
    const float* W; const float* asv; const float* adv; float* V; int li;
    if (idx < N1) { W = W1; asv = as1; adv = ad1; V = g_v1; li = idx; }
    else if (idx < N1 + N2) { W = W2; asv = as2; adv = ad2; V = g_v2; li = idx - N1; }
    else return;
    int k = li >> 4;
    int col = li & 15;
    int h = col & 7;
    const float* att = (col & 8) ? adv : asv;
    float acc = 0.f;
#pragma unroll 8
    for (int f = 0; f < F2C; f++)
        acc += W[(long)k * D1 + h * F2C + f] * att[h * F2C + f];
    V[li] = acc;
}

// ---------------- attention logits from input features ------------------------------
template <int K>
__global__ __launch_bounds__(256) void k_attnx(const float* __restrict__ feat,
                                               const float* __restrict__ V) {
    __shared__ float sV[K * 17];
    int tid = threadIdx.x;
    for (int idx = tid; idx < K * 16; idx += 256) {
        int k = idx >> 4, c = idx & 15;
        sV[k * 17 + c] = V[idx];
    }
    __syncthreads();
    int warp = tid >> 5, lane = tid & 31;
    int n = blockIdx.x * 8 + warp;
    if (n >= NN) return;
    float xv[K / 32];
#pragma unroll
    for (int c = 0; c < K / 32; c++) xv[c] = feat[(long)n * K + c * 32 + lane];
    float acc[16];
#pragma unroll
    for (int h = 0; h < 16; h++) acc[h] = 0.f;
#pragma unroll
    for (int c = 0; c < K / 32; c++) {
        int k = c * 32 + lane;
#pragma unroll
        for (int h = 0; h < 16; h++) acc[h] += xv[c] * sV[k * 17 + h];
    }
#pragma unroll
    for (int off = 16; off > 0; off >>= 1)
#pragma unroll
        for (int h = 0; h < 16; h++)
            acc[h] += __shfl_xor_sync(0xffffffffu, acc[h], off);
    if (lane == 0) {
#pragma unroll
        for (int h = 0; h < 8; h++) {
            g_as[n * HC + h] = acc[h];
            g_ad[n * HC + h] = acc[8 + h];
        }
    }
}

// ---------------- fused aggregation: stats + gather (+ optional softmax) -------------
// block = 128 threads per node; thread t: head h = t>>4, owns feats [4t,4t+4).
// SMAX=false: out = sum(alpha*h[src]) + bias (TO = bf16 or float)
// SMAX=true : out = softmax(sum + bias) over 512 (TO = float)
template <typename TO, bool SMAX>
__global__ __launch_bounds__(128) void k_agg(const __nv_bfloat16* __restrict__ hsrc,
                                             const float* __restrict__ bias,
                                             TO* __restrict__ out) {
    __shared__ float sAl[32][8];    // exp(e-m) per [chunk-edge][head]
    __shared__ int   sSrc[32];
    __shared__ float sMx[8], sInv[8], sAd[8];
    __shared__ float red[128];
    int n = blockIdx.x;
    int t = threadIdx.x;
    int h = t >> 4, sub = t & 15;
    int beg = g_offs[n], end = g_offs[n + 1];
    if (t < 8) sAd[t] = g_ad[n * HC + t];
    __syncthreads();
    float adn = sAd[h];

    // ---- phase 1: per-head online max/sum, 16 lanes per head ----
    float mx = -1e30f, s = 0.f;
    for (int j = beg + sub; j < end; j += 16) {
        float e = lrelu(g_as[g_csrc[j] * HC + h] + adn);
        float nm = fmaxf(mx, e);
        s = s * __expf(mx - nm) + __expf(e - nm);
        mx = nm;
    }
#pragma unroll
    for (int o = 8; o > 0; o >>= 1) {
        float mo = __shfl_xor_sync(0xffffffffu, mx, o, 16);
        float so = __shfl_xor_sync(0xffffffffu, s, o, 16);
        float nm = fmaxf(mx, mo);
        s = s * __expf(mx - nm) + so * __expf(mo - nm);
        mx = nm;
    }
    if (sub == 0) {
        sMx[h] = mx;
        sInv[h] = 1.0f / (s + 1e-16f);
    }
    __syncthreads();
    float mn  = sMx[h];
    float inv = sInv[h];

    // ---- phase 2: chunked alpha + accumulate ----
    float4 acc = make_float4(0.f, 0.f, 0.f, 0.f);
    for (int c0 = beg; c0 < end; c0 += 32) {
        int cnt = min(32, end - c0);
        __syncthreads();
        for (int v = t; v < cnt * 8; v += 128) {
            int c = v >> 3, hh = v & 7;
            int src = g_csrc[c0 + c];
            if (hh == 0) sSrc[c] = src;
            float e = lrelu(g_as[src * HC + hh] + sAd[hh]);
            sAl[c][hh] = __expf(e - sMx[hh]);
        }
        __syncthreads();
        for (int c = 0; c < cnt; c++) {
            float alpha = sAl[c][h];
            int src = sSrc[c];
            uint2 u = *(const uint2*)&hsrc[(long)src * D1 + t * 4];
            float2 p0 = __bfloat1622float2(*(__nv_bfloat162*)&u.x);
            float2 p1 = __bfloat1622float2(*(__nv_bfloat162*)&u.y);
            acc.x += alpha * p0.x;
            acc.y += alpha * p0.y;
            acc.z += alpha * p1.x;
            acc.w += alpha * p1.y;
        }
    }
    float4 b = *(const float4*)&bias[t * 4];
    acc.x = acc.x * inv + b.x;
    acc.y = acc.y * inv + b.y;
    acc.z = acc.z * inv + b.z;
    acc.w = acc.w * inv + b.w;

    if (!SMAX) {
        // store (bf16 or fp32)
        if (sizeof(TO) == 2) {
            uint2 u = make_uint2(packbf(acc.x, acc.y), packbf(acc.z, acc.w));
            *(uint2*)&out[(long)n * D1 + t * 4] = u;
        } else {
            *(float4*)&((float*)out)[(long)n * D1 + t * 4] = acc;
        }
        return;
    }

    // ---- fused row softmax over 512 (4 values per thread) ----
    float lm = fmaxf(fmaxf(acc.x, acc.y), fmaxf(acc.z, acc.w));
    red[t] = lm;
    __syncthreads();
#pragma unroll
    for (int o = 64; o > 0; o >>= 1) {
        if (t < o) red[t] = fmaxf(red[t], red[t + o]);
        __syncthreads();
    }
    float gm = red[0];
    __syncthreads();
    float e0 = __expf(acc.x - gm), e1 = __expf(acc.y - gm);
    float e2 = __expf(acc.z - gm), e3 = __expf(acc.w - gm);
    red[t] = e0 + e1 + e2 + e3;
    __syncthreads();
#pragma unroll
    for (int o = 64; o > 0; o >>= 1) {
        if (t < o) red[t] += red[t + o];
        __syncthreads();
    }
    float rinv = 1.0f / red[0];
    float* fout = (float*)out;
    *(float4*)&fout[(long)n * D1 + t * 4] =
        make_float4(e0 * rinv, e1 * rinv, e2 * rinv, e3 * rinv);
}

// ---------------- bf16 TN GEMM with ldmatrix fragments (R8-proven) --------------------
#define SROW 36

template <typename TO>
__device__ __forceinline__ void storeC2(TO* C, long idx, float a, float b);
template <>
__device__ __forceinline__ void storeC2<float>(float* C, long idx, float a, float b) {
    *(float2*)&C[idx] = make_float2(a, b);
}
template <>
__device__ __forceinline__ void storeC2<__nv_bfloat16>(__nv_bfloat16* C, long idx, float a, float b) {
    unsigned u = packbf(a, b);
    *(unsigned*)&C[idx] = u;
}

__device__ __forceinline__ void ldsm4(unsigned& r0, unsigned& r1, unsigned& r2, unsigned& r3,
                                      unsigned addr) {
    asm volatile("ldmatrix.sync.aligned.m8n8.x4.shared.b16 {%0,%1,%2,%3}, [%4];"
                 : "=r"(r0), "=r"(r1), "=r"(r2), "=r"(r3) : "r"(addr));
}

template <typename TO>
__global__ __launch_bounds__(256) void k_bgemm(int M, int N, int K,
                                               const __nv_bfloat16* __restrict__ A,
                                               const __nv_bfloat16* __restrict__ Bt,
                                               TO* __restrict__ C) {
    __shared__ unsigned As[128][SROW];
    __shared__ unsigned Bs[128][SROW];
    int tid  = threadIdx.x;
    int lane = tid & 31;
    int warp = tid >> 5;
    int wr = warp & 3;
    int wc = warp >> 2;
    int blockRow = blockIdx.y * 128;
    int blockCol = blockIdx.x * 128;

    float acc[2][8][4];
#pragma unroll
    for (int i = 0; i < 2; i++)
#pragma unroll
        for (int j = 0; j < 8; j++)
#pragma unroll
            for (int q = 0; q < 4; q++) acc[i][j][q] = 0.0f;

    unsigned asBase = (unsigned)__cvta_generic_to_shared(&As[0][0]);
    unsigned bsBase = (unsigned)__cvta_generic_to_shared(&Bs[0][0]);
    int sub = lane >> 3;
    int l7  = lane & 7;
    unsigned aAddr[2];
#pragma unroll
    for (int i = 0; i < 2; i++) {
        int row = wr * 32 + i * 16 + (sub & 1) * 8 + l7;
        aAddr[i] = asBase + row * (SROW * 4) + (sub >> 1) * 16;
    }
    unsigned bAddr[4];
#pragma unroll
    for (int jj = 0; jj < 4; jj++) {
        int tile = jj * 2 + (sub >> 1);
        int row = wc * 64 + tile * 8 + l7;
        bAddr[jj] = bsBase + row * (SROW * 4) + (sub & 1) * 16;
    }

    uint4 pa[2], pb[2];
#pragma unroll
    for (int i = 0; i < 2; i++) {
        int idx = tid + i * 256;
        int r = idx >> 2, c = idx & 3;
        pa[i] = make_uint4(0, 0, 0, 0);
        if (blockRow + r < M)
            pa[i] = *(const uint4*)&A[(long)(blockRow + r) * K + c * 8];
        pb[i] = *(const uint4*)&Bt[(long)(blockCol + r) * K + c * 8];
    }

    for (int k0 = 0; k0 < K; k0 += 32) {
#pragma unroll
        for (int i = 0; i < 2; i++) {
            int idx = tid + i * 256;
            int r = idx >> 2, c = idx & 3;
            *(uint4*)&As[r][c * 4] = pa[i];
            *(uint4*)&Bs[r][c * 4] = pb[i];
        }
        __syncthreads();

        if (k0 + 32 < K) {
#pragma unroll
            for (int i = 0; i < 2; i++) {
                int idx = tid + i * 256;
                int r = idx >> 2, c = idx & 3;
                pa[i] = make_uint4(0, 0, 0, 0);
                if (blockRow + r < M)
                    pa[i] = *(const uint4*)&A[(long)(blockRow + r) * K + k0 + 32 + c * 8];
                pb[i] = *(const uint4*)&Bt[(long)(blockCol + r) * K + k0 + 32 + c * 8];
            }
        }

#pragma unroll
        for (int ks = 0; ks < 2; ks++) {
            unsigned kadd = ks * 32;
            unsigned a[2][4], b[8][2];
#pragma unroll
            for (int i = 0; i < 2; i++)
                ldsm4(a[i][0], a[i][1], a[i][2], a[i][3], aAddr[i] + kadd);
#pragma unroll
            for (int jj = 0; jj < 4; jj++)
                ldsm4(b[jj * 2][0], b[jj * 2][1], b[jj * 2 + 1][0], b[jj * 2 + 1][1],
                      bAddr[jj] + kadd);
#pragma unroll
            for (int i = 0; i < 2; i++) {
#pragma unroll
                for (int j = 0; j < 8; j++) {
                    asm volatile(
                        "mma.sync.aligned.m16n8k16.row.col.f32.bf16.bf16.f32 "
                        "{%0,%1,%2,%3}, {%4,%5,%6,%7}, {%8,%9}, {%0,%1,%2,%3};"
                        : "+f"(acc[i][j][0]), "+f"(acc[i][j][1]),
                          "+f"(acc[i][j][2]), "+f"(acc[i][j][3])
                        : "r"(a[i][0]), "r"(a[i][1]), "r"(a[i][2]), "r"(a[i][3]),
                          "r"(b[j][0]), "r"(b[j][1]));
                }
            }
        }
        __syncthreads();
    }

#pragma unroll
    for (int i = 0; i < 2; i++) {
        int r = blockRow + wr * 32 + i * 16 + (lane >> 2);
#pragma unroll
        for (int j = 0; j < 8; j++) {
            int c = blockCol + wc * 64 + j * 8 + (lane & 3) * 2;
            if (r < M)
                storeC2<TO>(C, (long)r * N + c, acc[i][j][0], acc[i][j][1]);
            if (r + 8 < M)
                storeC2<TO>(C, (long)(r + 8) * N + c, acc[i][j][2], acc[i][j][3]);
        }
    }
}

// ---------------- LSTM elementwise + relu; dual-format output --------------------------
__global__ void k_lstm(const float* __restrict__ b_ih, const float* __restrict__ b_hh) {
    int idx = blockIdx.x * blockDim.x + threadIdx.x;
    if (idx >= NN * F2C) return;
    int n = idx >> 6, j = idx & 63;
    const float* g = g_gates + (long)n * G4;
    float i_ = g[j]       + b_ih[j]       + b_hh[j];
    float gg = g[128 + j] + b_ih[128 + j] + b_hh[128 + j];
    float o_ = g[192 + j] + b_ih[192 + j] + b_hh[192 + j];
    float c  = sigf(i_) * tanhf(gg);
    float hh = sigf(o_) * tanhf(c);
    float r  = fmaxf(hh, 0.0f);
    g_h2[idx]  = r;
    g_h2b[idx] = __float2bfloat16(r);
}

// ---------------- launch ------------------------------------------------------------------
extern "C" void kernel_launch(void* const* d_in, const int* in_sizes, int n_in,
                              void* d_out, int out_size) {
    const float* x        = (const float*)d_in[0];
    const int*   ei       = (const int*)d_in[1];
    const float* W1       = (const float*)d_in[3];
    const float* att_src1 = (const float*)d_in[4];
    const float* att_dst1 = (const float*)d_in[5];
    const float* bias1    = (const float*)d_in[6];
    const float* W_ih     = (const float*)d_in[7];
    const float* b_ih     = (const float*)d_in[9];
    const float* b_hh     = (const float*)d_in[10];
    const float* W2       = (const float*)d_in[11];
    const float* att_src2 = (const float*)d_in[12];
    const float* att_dst2 = (const float*)d_in[13];
    const float* bias2    = (const float*)d_in[14];
    float* out = (float*)d_out;

    int E = in_sizes[1] / 2;
    int etot = E + NN;

    void* p_deg = nullptr;   cudaGetSymbolAddress(&p_deg, g_deg);
    void* p_v1 = nullptr;    cudaGetSymbolAddress(&p_v1, g_v1);
    void* p_v2 = nullptr;    cudaGetSymbolAddress(&p_v2, g_v2);
    void* p_xb = nullptr;    cudaGetSymbolAddress(&p_xb, g_xb);
    void* p_W1b = nullptr;   cudaGetSymbolAddress(&p_W1b, g_W1b);
    void* p_Wihb = nullptr;  cudaGetSymbolAddress(&p_Wihb, g_Wihb);
    void* p_W2b = nullptr;   cudaGetSymbolAddress(&p_W2b, g_W2b);
    void* p_h1b = nullptr;   cudaGetSymbolAddress(&p_h1b, g_h1b);
    void* p_agg1b = nullptr; cudaGetSymbolAddress(&p_agg1b, g_agg1b);
    void* p_gates = nullptr; cudaGetSymbolAddress(&p_gates, g_gates);
    void* p_h2 = nullptr;    cudaGetSymbolAddress(&p_h2, g_h2);
    void* p_h2b = nullptr;   cudaGetSymbolAddress(&p_h2b, g_h2b);
    void* p_h3b = nullptr;   cudaGetSymbolAddress(&p_h3b, g_h3b);

    cudaMemsetAsync(p_deg, 0, NN * sizeof(int), 0);
    k_cvt<<<(NN * FIN / 4 + 255) / 256, 256>>>(x, (__nv_bfloat16*)p_xb, NN * FIN / 4);
    k_prepw<<<((FIN + G4 + F2C) * D1 + 255) / 256, 256>>>(W1, W_ih, W2);
    k_degree<<<(etot + 255) / 256, 256>>>(ei, E);

    // GEMM1 (launch #5, profiled): h1b = xb @ W1b^T
    {
        dim3 grid(D1 / 128, (NN + 127) / 128);
        k_bgemm<__nv_bfloat16><<<grid, 256>>>(NN, D1, FIN, (const __nv_bfloat16*)p_xb,
                                              (const __nv_bfloat16*)p_W1b,
                                              (__nv_bfloat16*)p_h1b);
    }

    k_scan<<<1, 1024>>>();
    k_scatter<<<(etot + 255) / 256, 256>>>(ei, E);
    k_folds<<<((FIN + F2C) * 16 + 255) / 256, 256>>>(W1, att_src1, att_dst1,
                                                     W2, att_src2, att_dst2);

    // ---- layer 1 ----
    k_attnx<FIN><<<2500, 256>>>(x, (const float*)p_v1);
    k_agg<__nv_bfloat16, false><<<NN, 128>>>((const __nv_bfloat16*)p_h1b, bias1,
                                             (__nv_bfloat16*)p_agg1b);
    // GEMM2: gates = agg1b @ W_ih^T
    {
        dim3 grid(G4 / 128, (NN + 127) / 128);
        k_bgemm<float><<<grid, 256>>>(NN, G4, D1, (const __nv_bfloat16*)p_agg1b,
                                      (const __nv_bfloat16*)p_Wihb, (float*)p_gates);
    }
    k_lstm<<<(NN * F2C + 255) / 256, 256>>>(b_ih, b_hh);

    // ---- layer 2 ----
    // GEMM3: h3b = h2b @ W2b^T
    {
        dim3 grid(D1 / 128, (NN + 127) / 128);
        k_bgemm<__nv_bfloat16><<<grid, 256>>>(NN, D1, F2C, (const __nv_bfloat16*)p_h2b,
                                              (const __nv_bfloat16*)p_W2b,
                                              (__nv_bfloat16*)p_h3b);
    }
    k_attnx<F2C><<<2500, 256>>>((const float*)p_h2, (const float*)p_v2);
    // fused gather + bias2 + softmax -> out
    k_agg<float, true><<<NN, 128>>>((const __nv_bfloat16*)p_h3b, bias2, out);
}